// round 7
// baseline (speedup 1.0000x reference)
#include <cuda_runtime.h>
#include <cuda_bf16.h>
#include <cstdint>

// Problem constants
#define BB    2
#define NQ    4096
#define NS    8
#define NTOT  4104          // NQ + NS
#define CC    192
#define HH    8
#define DD    24            // CC / HH
#define MROWS (BB*NTOT)     // 8208
#define NKP   4224          // padded to 33*128
#define QTILES 33           // q-tiles of 128
#define KTILES 65           // ceil(4104/64)
#define LOG2E 1.4426950408889634f

// ---------------------------------------------------------------------------
// helpers
// ---------------------------------------------------------------------------
__device__ __forceinline__ float ex2f(float x) {
    float r; asm("ex2.approx.f32 %0, %1;" : "=f"(r) : "f"(x)); return r;
}
__device__ __forceinline__ uint32_t cvt_bf2(float hi, float lo) {
    uint32_t r; asm("cvt.rn.bf16x2.f32 %0, %1, %2;" : "=r"(r) : "f"(hi), "f"(lo)); return r;
}
__device__ __forceinline__ void hmma(float (&c)[4],
                                     uint32_t a0, uint32_t a1, uint32_t a2, uint32_t a3,
                                     uint32_t b0, uint32_t b1) {
    asm volatile(
        "mma.sync.aligned.m16n8k16.row.col.f32.bf16.bf16.f32 "
        "{%0,%1,%2,%3},{%4,%5,%6,%7},{%8,%9},{%0,%1,%2,%3};"
        : "+f"(c[0]), "+f"(c[1]), "+f"(c[2]), "+f"(c[3])
        : "r"(a0), "r"(a1), "r"(a2), "r"(a3), "r"(b0), "r"(b1));
}
__device__ __forceinline__ uint32_t smem_u32(const void* p) {
    uint32_t a;
    asm("{ .reg .u64 t; cvta.to.shared.u64 t, %1; cvt.u32.u64 %0, t; }" : "=r"(a) : "l"(p));
    return a;
}
__device__ __forceinline__ void ldsm_x2(uint32_t& r0, uint32_t& r1, uint32_t addr) {
    asm volatile("ldmatrix.sync.aligned.m8n8.x2.shared.b16 {%0,%1}, [%2];"
                 : "=r"(r0), "=r"(r1) : "r"(addr));
}
__device__ __forceinline__ void ldsm_x2_t(uint32_t& r0, uint32_t& r1, uint32_t addr) {
    asm volatile("ldmatrix.sync.aligned.m8n8.x2.trans.shared.b16 {%0,%1}, [%2];"
                 : "=r"(r0), "=r"(r1) : "r"(addr));
}
#define CP16(dst, src) \
    asm volatile("cp.async.cg.shared.global [%0], [%1], 16;" :: "r"(dst), "l"(src))
#define CP_COMMIT() asm volatile("cp.async.commit_group;" ::: "memory")
#define CP_WAIT(n)  asm volatile("cp.async.wait_group %0;" :: "n"(n) : "memory")

// ---------------------------------------------------------------------------
// Scratch (device globals; zero-initialized -> padding rows stay 0)
// ---------------------------------------------------------------------------
__device__ __align__(16) __nv_bfloat16 g_Qh[16*NKP*32];
__device__ __align__(16) __nv_bfloat16 g_Ql[16*NKP*32];
__device__ __align__(16) __nv_bfloat16 g_Kh[16*NKP*32];
__device__ __align__(16) __nv_bfloat16 g_Kl[16*NKP*32];
__device__ __align__(16) __nv_bfloat16 g_Vh[16*NKP*32];   // key-major like K
__device__ __align__(16) __nv_bfloat16 g_Vl[16*NKP*32];
__device__ __align__(16) float g_O[BB*NTOT*CC];

// ---------------------------------------------------------------------------
// 1) QKV projection (concat fused) + bf16 hi/lo split epilogue (all packed u32).
// ---------------------------------------------------------------------------
__global__ __launch_bounds__(256)
void qkv_gemm_kernel(const float* __restrict__ X,
                     const float* __restrict__ S,
                     const float* __restrict__ W,
                     const float* __restrict__ T) {
    __shared__ float As[16][64];
    __shared__ float Ws[16][64];

    const int tx = threadIdx.x;
    const int ty = threadIdx.y;
    const int t  = ty * 16 + tx;
    const int row0 = blockIdx.x * 64;
    const int col0 = blockIdx.y * 64;

    float acc[4][4];
    #pragma unroll
    for (int i = 0; i < 4; i++)
        #pragma unroll
        for (int j = 0; j < 4; j++) acc[i][j] = 0.f;

    const int lr  = t >> 2;
    const int lc4 = t & 3;

    const float* Arow = nullptr;
    {
        int gr = row0 + lr;
        if (gr < MROWS) {
            int b = (gr >= NTOT) ? 1 : 0;
            int n = gr - b * NTOT;
            if (n < NQ) Arow = X + (size_t)(b * NQ + n) * CC;
            else        Arow = S + (size_t)(b * NS + (n - NQ)) * CC;
        }
    }

    for (int k0 = 0; k0 < CC; k0 += 16) {
        {
            float4 a = make_float4(0.f, 0.f, 0.f, 0.f);
            if (Arow) a = *reinterpret_cast<const float4*>(Arow + k0 + lc4 * 4);
            As[lc4*4+0][lr] = a.x; As[lc4*4+1][lr] = a.y;
            As[lc4*4+2][lr] = a.z; As[lc4*4+3][lr] = a.w;
        }
        {
            float4 w = *reinterpret_cast<const float4*>(&W[(col0 + lr) * CC + k0 + lc4 * 4]);
            Ws[lc4*4+0][lr] = w.x; Ws[lc4*4+1][lr] = w.y;
            Ws[lc4*4+2][lr] = w.z; Ws[lc4*4+3][lr] = w.w;
        }
        __syncthreads();
        #pragma unroll
        for (int kk = 0; kk < 16; ++kk) {
            float4 a = *reinterpret_cast<const float4*>(&As[kk][ty * 4]);
            float4 w = *reinterpret_cast<const float4*>(&Ws[kk][tx * 4]);
            float av[4] = {a.x, a.y, a.z, a.w};
            float wv[4] = {w.x, w.y, w.z, w.w};
            #pragma unroll
            for (int i = 0; i < 4; i++)
                #pragma unroll
                for (int j = 0; j < 4; j++)
                    acc[i][j] = fmaf(av[i], wv[j], acc[i][j]);
        }
        __syncthreads();
    }

    #pragma unroll
    for (int i = 0; i < 4; i++) {
        int m = row0 + ty * 4 + i;
        if (m >= MROWS) continue;
        int b = (m >= NTOT) ? 1 : 0;
        int n = m - b * NTOT;
        #pragma unroll
        for (int j2 = 0; j2 < 4; j2 += 2) {
            int o = col0 + tx * 4 + j2;        // even
            float v0 = acc[i][j2], v1 = acc[i][j2 + 1];
            __nv_bfloat16* dstH;
            __nv_bfloat16* dstL;
            int oo;
            float sc = 1.f;
            if (o < CC)          { dstH = g_Qh; dstL = g_Ql; oo = o;          sc = T[o / DD] * LOG2E; }
            else if (o < 2 * CC) { dstH = g_Kh; dstL = g_Kl; oo = o - CC; }
            else                 { dstH = g_Vh; dstL = g_Vl; oo = o - 2 * CC; }
            int hh = oo / DD, d = oo % DD;
            float a0 = v0 * sc, a1 = v1 * sc;
            uint32_t hp = cvt_bf2(a1, a0);
            float r0 = a0 - __uint_as_float(hp << 16);
            float r1 = a1 - __uint_as_float(hp & 0xffff0000u);
            uint32_t lp = cvt_bf2(r1, r0);
            size_t idx = ((size_t)(b * HH + hh) * NKP + n) * 32 + d;
            *reinterpret_cast<uint32_t*>(dstH + idx) = hp;
            *reinterpret_cast<uint32_t*>(dstL + idx) = lp;
        }
    }
}

// ---------------------------------------------------------------------------
// 2) Attention: flash, mma.sync bf16 hi/lo split, ldmatrix fragments,
//    cp.async double buffering. 256 threads, 128 queries (16 rows/warp).
// smem layout (bytes):
//   0      : Qh 128x80     10240
//   10240  : Ql 128x80     10240
//   20480 + s*20480 (s=0,1):
//     +0      Kh 64x80      5120
//     +5120   Kl 64x80      5120
//     +10240  Vh 64x80      5120
//     +15360  Vl 64x80      5120
// total 61440
// ---------------------------------------------------------------------------
#define OQH 0
#define OQL 10240
#define OKV 20480
#define STG 20480
#define OKH 0
#define OKL 5120
#define OVH 10240
#define OVL 15360
#define ATT_SMEM 61440

__global__ __launch_bounds__(256, 2)
void attn_kernel() {
    extern __shared__ __align__(16) uint8_t dsm[];
    const uint32_t sb = smem_u32(dsm);

    const int tid = threadIdx.x;
    const int w   = tid >> 5;
    const int t   = tid & 31;
    const int bh  = blockIdx.z * HH + blockIdx.y;
    const int q0  = blockIdx.x * 128;

    // ---- issue Q loads (row = tid/2, two 16B groups each) ----
    {
        int row = tid >> 1;
        const __nv_bfloat16* qh = g_Qh + ((size_t)bh * NKP + q0 + row) * 32;
        const __nv_bfloat16* ql = g_Ql + ((size_t)bh * NKP + q0 + row) * 32;
        #pragma unroll
        for (int u = 0; u < 2; u++) {
            int g = (tid & 1) * 2 + u;
            CP16(sb + OQH + row * 80 + g * 16, qh + g * 8);
            CP16(sb + OQL + row * 80 + g * 16, ql + g * 8);
        }
    }
    // K/V loader mapping: arr = tid>>6 (Kh,Kl,Vh,Vl), row = tid&63, 4 groups
    const int larr = tid >> 6;
    const int lrow = tid & 63;
    const __nv_bfloat16* lsrc =
        (larr == 0) ? g_Kh : (larr == 1) ? g_Kl : (larr == 2) ? g_Vh : g_Vl;
    const uint32_t ldst = (larr == 0) ? OKH : (larr == 1) ? OKL : (larr == 2) ? OVH : OVL;
    {
        const __nv_bfloat16* src = lsrc + ((size_t)bh * NKP + lrow) * 32;
        uint32_t dst = sb + OKV + ldst + lrow * 80;
        #pragma unroll
        for (int g = 0; g < 4; g++) CP16(dst + g * 16, src + g * 8);
    }
    CP_COMMIT();

    uint32_t aQ[2][2][4];      // [src h/l][kstep][frag]
    float O[3][4];
    float lsum[2] = {0.f, 0.f};
    #pragma unroll
    for (int nt = 0; nt < 3; nt++)
        #pragma unroll
        for (int c = 0; c < 4; c++) O[nt][c] = 0.f;

    for (int kt = 0; kt < KTILES; ++kt) {
        if (kt + 1 < KTILES) {
            const int j1 = (kt + 1) * 64;
            const __nv_bfloat16* src = lsrc + ((size_t)bh * NKP + j1 + lrow) * 32;
            uint32_t dst = sb + OKV + ((kt + 1) & 1) * STG + ldst + lrow * 80;
            #pragma unroll
            for (int g = 0; g < 4; g++) CP16(dst + g * 16, src + g * 8);
            CP_COMMIT();
            CP_WAIT(1);
        } else {
            CP_WAIT(0);
        }
        __syncthreads();

        if (kt == 0) {
            // preload Q A-fragments
            int r = w * 16 + (t >> 2);
            #pragma unroll
            for (int s = 0; s < 2; s++) {
                int off = s * 32 + (t & 3) * 4;
                const uint8_t* qh = dsm + OQH + r * 80 + off;
                const uint8_t* ql = dsm + OQL + r * 80 + off;
                aQ[0][s][0] = *reinterpret_cast<const uint32_t*>(qh);
                aQ[0][s][1] = *reinterpret_cast<const uint32_t*>(qh + 8 * 80);
                aQ[0][s][2] = *reinterpret_cast<const uint32_t*>(qh + 16);
                aQ[0][s][3] = *reinterpret_cast<const uint32_t*>(qh + 8 * 80 + 16);
                aQ[1][s][0] = *reinterpret_cast<const uint32_t*>(ql);
                aQ[1][s][1] = *reinterpret_cast<const uint32_t*>(ql + 8 * 80);
                aQ[1][s][2] = *reinterpret_cast<const uint32_t*>(ql + 16);
                aQ[1][s][3] = *reinterpret_cast<const uint32_t*>(ql + 8 * 80 + 16);
            }
        }

        const uint32_t kb = sb + OKV + (kt & 1) * STG;
        const int j0 = kt * 64;

        // ---- S = qh*kh + ql*kh + qh*kl  (16 rows x 64 keys per warp) ----
        float C[8][4];
        #pragma unroll
        for (int nt = 0; nt < 8; nt++)
            #pragma unroll
            for (int c = 0; c < 4; c++) C[nt][c] = 0.f;

        // ldmatrix lane address components (same for every nt/s, shifted)
        const uint32_t krow_off = (uint32_t)(t & 7) * 80 + (((t >> 3) & 1) ? 16u : 0u);

        #pragma unroll
        for (int c3 = 0; c3 < 3; c3++) {
            const uint32_t bBase = kb + ((c3 == 2) ? OKL : OKH);
            const int aI = (c3 == 1) ? 1 : 0;
            #pragma unroll
            for (int s = 0; s < 2; s++) {
                uint32_t b0[8], b1[8];
                #pragma unroll
                for (int nt = 0; nt < 8; nt++)
                    ldsm_x2(b0[nt], b1[nt], bBase + (uint32_t)nt * 8 * 80 + s * 32 + krow_off);
                #pragma unroll
                for (int nt = 0; nt < 8; nt++)
                    hmma(C[nt], aQ[aI][s][0], aQ[aI][s][1], aQ[aI][s][2], aQ[aI][s][3],
                         b0[nt], b1[nt]);
            }
        }

        // ---- softmax + split P to bf16 hi/lo ----
        uint32_t PH[4][4], PL[4][4];
        const bool edge = (j0 + 64 > NTOT);
        #pragma unroll
        for (int nt = 0; nt < 8; nt++) {
            float p0 = ex2f(C[nt][0]);
            float p1 = ex2f(C[nt][1]);
            float p2 = ex2f(C[nt][2]);
            float p3 = ex2f(C[nt][3]);
            if (edge) {
                int key0 = j0 + nt * 8 + (t & 3) * 2;
                if (key0     >= NTOT) { p0 = 0.f; p2 = 0.f; }
                if (key0 + 1 >= NTOT) { p1 = 0.f; p3 = 0.f; }
            }
            lsum[0] += p0 + p1;
            lsum[1] += p2 + p3;
            uint32_t h01 = cvt_bf2(p1, p0);
            float r0 = p0 - __uint_as_float(h01 << 16);
            float r1 = p1 - __uint_as_float(h01 & 0xffff0000u);
            uint32_t l01 = cvt_bf2(r1, r0);
            uint32_t h23 = cvt_bf2(p3, p2);
            float r2 = p2 - __uint_as_float(h23 << 16);
            float r3 = p3 - __uint_as_float(h23 & 0xffff0000u);
            uint32_t l23 = cvt_bf2(r3, r2);
            int ks = nt >> 1, half = nt & 1;
            PH[ks][half * 2 + 0] = h01;
            PH[ks][half * 2 + 1] = h23;
            PL[ks][half * 2 + 0] = l01;
            PL[ks][half * 2 + 1] = l23;
        }

        // ---- O += ph*vh + ph*vl + pl*vh  (V via ldmatrix.trans) ----
        const uint32_t vrow_off = (uint32_t)(t & 15) * 80;
        #pragma unroll
        for (int ks = 0; ks < 4; ks++) {
            #pragma unroll
            for (int nt = 0; nt < 3; nt++) {
                uint32_t vh0, vh1, vl0, vl1;
                uint32_t base = (uint32_t)(ks * 16) * 80 + nt * 16 + vrow_off;
                ldsm_x2_t(vh0, vh1, kb + OVH + base);
                ldsm_x2_t(vl0, vl1, kb + OVL + base);
                hmma(O[nt], PH[ks][0], PH[ks][1], PH[ks][2], PH[ks][3], vh0, vh1);
                hmma(O[nt], PH[ks][0], PH[ks][1], PH[ks][2], PH[ks][3], vl0, vl1);
                hmma(O[nt], PL[ks][0], PL[ks][1], PL[ks][2], PL[ks][3], vh0, vh1);
            }
        }
        __syncthreads();
    }

    // ---- reduce row sums over quad lanes, invert ----
    #pragma unroll
    for (int hf = 0; hf < 2; hf++) {
        float v = lsum[hf];
        v += __shfl_xor_sync(0xffffffffu, v, 1);
        v += __shfl_xor_sync(0xffffffffu, v, 2);
        lsum[hf] = 1.f / v;
    }

    // ---- epilogue: O / l -> g_O ----
    #pragma unroll
    for (int c = 0; c < 4; c++) {
        int row = w * 16 + (t >> 2) + ((c >> 1) ? 8 : 0);
        int q = q0 + row;
        if (q < NTOT) {
            float inv = lsum[c >> 1];
            #pragma unroll
            for (int nt = 0; nt < 3; nt++) {
                int d = blockIdx.y * DD + nt * 8 + (t & 3) * 2 + (c & 1);
                g_O[(size_t)(blockIdx.z * NTOT + q) * CC + d] = O[nt][c] * inv;
            }
        }
    }
}

// ---------------------------------------------------------------------------
// 3) Output projection: out[b,n,o] = sum_c O[b,n,c] * Wout[o,c], n < NQ only.
// ---------------------------------------------------------------------------
__global__ __launch_bounds__(256)
void out_gemm_kernel(const float* __restrict__ W, float* __restrict__ out) {
    __shared__ float As[16][64];
    __shared__ float Ws[16][64];

    const int tx = threadIdx.x;
    const int ty = threadIdx.y;
    const int t  = ty * 16 + tx;
    const int row0 = blockIdx.x * 64;
    const int col0 = blockIdx.y * 64;

    float acc[4][4];
    #pragma unroll
    for (int i = 0; i < 4; i++)
        #pragma unroll
        for (int j = 0; j < 4; j++) acc[i][j] = 0.f;

    const int lr  = t >> 2;
    const int lc4 = t & 3;

    for (int k0 = 0; k0 < CC; k0 += 16) {
        {
            int m = row0 + lr;
            int b = m >> 12;
            int n = m & 4095;
            float4 a = *reinterpret_cast<const float4*>(
                &g_O[(size_t)(b * NTOT + n) * CC + k0 + lc4 * 4]);
            As[lc4*4+0][lr] = a.x; As[lc4*4+1][lr] = a.y;
            As[lc4*4+2][lr] = a.z; As[lc4*4+3][lr] = a.w;
        }
        {
            float4 w = *reinterpret_cast<const float4*>(&W[(col0 + lr) * CC + k0 + lc4 * 4]);
            Ws[lc4*4+0][lr] = w.x; Ws[lc4*4+1][lr] = w.y;
            Ws[lc4*4+2][lr] = w.z; Ws[lc4*4+3][lr] = w.w;
        }
        __syncthreads();
        #pragma unroll
        for (int kk = 0; kk < 16; ++kk) {
            float4 a = *reinterpret_cast<const float4*>(&As[kk][ty * 4]);
            float4 w = *reinterpret_cast<const float4*>(&Ws[kk][tx * 4]);
            float av[4] = {a.x, a.y, a.z, a.w};
            float wv[4] = {w.x, w.y, w.z, w.w};
            #pragma unroll
            for (int i = 0; i < 4; i++)
                #pragma unroll
                for (int j = 0; j < 4; j++)
                    acc[i][j] = fmaf(av[i], wv[j], acc[i][j]);
        }
        __syncthreads();
    }

    #pragma unroll
    for (int i = 0; i < 4; i++) {
        int m = row0 + ty * 4 + i;
        #pragma unroll
        for (int j = 0; j < 4; j++) {
            int o = col0 + tx * 4 + j;
            out[(size_t)m * CC + o] = acc[i][j];
        }
    }
}

// ---------------------------------------------------------------------------
// launch
// ---------------------------------------------------------------------------
extern "C" void kernel_launch(void* const* d_in, const int* in_sizes, int n_in,
                              void* d_out, int out_size) {
    const float* X  = nullptr;
    const float* S  = nullptr;
    const float* Wq = nullptr;
    const float* Wo = nullptr;
    const float* T  = nullptr;
    for (int i = 0; i < n_in; i++) {
        switch (in_sizes[i]) {
            case BB * NQ * CC:  X  = (const float*)d_in[i]; break;
            case BB * NS * CC:  S  = (const float*)d_in[i]; break;
            case 3 * CC * CC:   Wq = (const float*)d_in[i]; break;
            case CC * CC:       Wo = (const float*)d_in[i]; break;
            case HH:            T  = (const float*)d_in[i]; break;
        }
    }

    // 1) QKV projection (concat fused, split epilogue)
    {
        dim3 grid((MROWS + 63) / 64, (3 * CC) / 64);   // (129, 9)
        dim3 blk(16, 16);
        qkv_gemm_kernel<<<grid, blk>>>(X, S, Wq, T);
    }
    // 2) attention (mma.sync bf16 split, ldmatrix, cp.async pipelined)
    {
        cudaFuncSetAttribute(attn_kernel, cudaFuncAttributeMaxDynamicSharedMemorySize, ATT_SMEM);
        dim3 grid(QTILES, HH, BB);                      // (33, 8, 2)
        attn_kernel<<<grid, 256, ATT_SMEM>>>();
    }
    // 3) output projection
    {
        dim3 grid((BB * NQ) / 64, CC / 64);             // (128, 3)
        dim3 blk(16, 16);
        out_gemm_kernel<<<grid, blk>>>(Wo, (float*)d_out);
    }
}

// round 10
// speedup vs baseline: 1.0726x; 1.0726x over previous
#include <cuda_runtime.h>
#include <cuda_bf16.h>
#include <cuda_fp16.h>
#include <cstdint>

// Problem constants
#define BB    2
#define NQ    4096
#define NS    8
#define NTOT  4104          // NQ + NS
#define CC    192
#define HH    8
#define DD    24            // CC / HH
#define MROWS (BB*NTOT)     // 8208
#define NKP   4224          // padded to 33*128
#define QTILES 33           // q-tiles of 128
#define KTILES 65           // ceil(4104/64)
#define LOG2E 1.4426950408889634f

// packed row widths (elements)
#define QK_COLS 88          // 80 data cols (5 ksteps x16) + 8 pad; 176B rows
#define V_COLS  40          // fp16, 24 real + pad; 80B rows

typedef unsigned long long u64;

// ---------------------------------------------------------------------------
// helpers
// ---------------------------------------------------------------------------
__device__ __forceinline__ float ex2f(float x) {
    float r; asm("ex2.approx.f32 %0, %1;" : "=f"(r) : "f"(x)); return r;
}
__device__ __forceinline__ uint32_t cvt_bf2(float hi, float lo) {
    uint32_t r; asm("cvt.rn.bf16x2.f32 %0, %1, %2;" : "=r"(r) : "f"(hi), "f"(lo)); return r;
}
// packed f32x2 helpers (sm_100+)
__device__ __forceinline__ u64 pack2f(float x, float y) {
    u64 r; asm("mov.b64 %0, {%1,%2};" : "=l"(r) : "f"(x), "f"(y)); return r;
}
__device__ __forceinline__ void unpack2f(u64 v, float& lo, float& hi) {
    asm("mov.b64 {%0,%1}, %2;" : "=f"(lo), "=f"(hi) : "l"(v));
}
__device__ __forceinline__ void fma2(u64& d, u64 a, u64 b) {
    asm("fma.rn.f32x2 %0, %1, %2, %0;" : "+l"(d) : "l"(a), "l"(b));
}
// bf16 mma (S pass)
__device__ __forceinline__ void hmma_bf(float (&c)[4],
                                        uint32_t a0, uint32_t a1, uint32_t a2, uint32_t a3,
                                        uint32_t b0, uint32_t b1) {
    asm volatile(
        "mma.sync.aligned.m16n8k16.row.col.f32.bf16.bf16.f32 "
        "{%0,%1,%2,%3},{%4,%5,%6,%7},{%8,%9},{%0,%1,%2,%3};"
        : "+f"(c[0]), "+f"(c[1]), "+f"(c[2]), "+f"(c[3])
        : "r"(a0), "r"(a1), "r"(a2), "r"(a3), "r"(b0), "r"(b1));
}
// fp16 mma (PV pass)
__device__ __forceinline__ void hmma_f16(float (&c)[4],
                                         uint32_t a0, uint32_t a1, uint32_t a2, uint32_t a3,
                                         uint32_t b0, uint32_t b1) {
    asm volatile(
        "mma.sync.aligned.m16n8k16.row.col.f32.f16.f16.f32 "
        "{%0,%1,%2,%3},{%4,%5,%6,%7},{%8,%9},{%0,%1,%2,%3};"
        : "+f"(c[0]), "+f"(c[1]), "+f"(c[2]), "+f"(c[3])
        : "r"(a0), "r"(a1), "r"(a2), "r"(a3), "r"(b0), "r"(b1));
}
__device__ __forceinline__ uint32_t smem_u32(const void* p) {
    uint32_t a;
    asm("{ .reg .u64 t; cvta.to.shared.u64 t, %1; cvt.u32.u64 %0, t; }" : "=r"(a) : "l"(p));
    return a;
}
__device__ __forceinline__ void ldsm_x2(uint32_t& r0, uint32_t& r1, uint32_t addr) {
    asm volatile("ldmatrix.sync.aligned.m8n8.x2.shared.b16 {%0,%1}, [%2];"
                 : "=r"(r0), "=r"(r1) : "r"(addr));
}
__device__ __forceinline__ void ldsm_x2_t(uint32_t& r0, uint32_t& r1, uint32_t addr) {
    asm volatile("ldmatrix.sync.aligned.m8n8.x2.trans.shared.b16 {%0,%1}, [%2];"
                 : "=r"(r0), "=r"(r1) : "r"(addr));
}
#define CP16(dst, src) \
    asm volatile("cp.async.cg.shared.global [%0], [%1], 16;" :: "r"(dst), "l"(src))
#define CP_COMMIT() asm volatile("cp.async.commit_group;" ::: "memory")
#define CP_WAIT(n)  asm volatile("cp.async.wait_group %0;" :: "n"(n) : "memory")

// ---------------------------------------------------------------------------
// Scratch (device globals; zero-initialized -> pad columns/rows stay 0)
// g_Qp rows: [qh(0:24) | ql(24:48) | qh(48:72) | 0(72:88)]   (bf16, temp*log2e folded)
// g_Kp rows: [kh(0:24) | kh(24:48) | kl(48:72) | 0(72:88)]   (bf16)
// g_Vf rows: [v(0:24) fp16 | 0]                               (fp16)
// ---------------------------------------------------------------------------
__device__ __align__(16) __nv_bfloat16 g_Qp[16*NKP*QK_COLS];
__device__ __align__(16) __nv_bfloat16 g_Kp[16*NKP*QK_COLS];
__device__ __align__(16) __half        g_Vf[16*NKP*V_COLS];
__device__ __align__(16) float g_O[BB*NTOT*CC];

// ---------------------------------------------------------------------------
// 1) QKV projection (concat fused) + packed split epilogue. FFMA2 inner loop.
// ---------------------------------------------------------------------------
__global__ __launch_bounds__(256)
void qkv_gemm_kernel(const float* __restrict__ X,
                     const float* __restrict__ S,
                     const float* __restrict__ W,
                     const float* __restrict__ T) {
    __shared__ float As[16][64];
    __shared__ float Ws[16][64];

    const int tx = threadIdx.x;
    const int ty = threadIdx.y;
    const int t  = ty * 16 + tx;
    const int row0 = blockIdx.x * 64;
    const int col0 = blockIdx.y * 64;

    u64 acc2[4][2];
    #pragma unroll
    for (int i = 0; i < 4; i++) { acc2[i][0] = 0ull; acc2[i][1] = 0ull; }

    const int lr  = t >> 2;
    const int lc4 = t & 3;

    const float* Arow = nullptr;
    {
        int gr = row0 + lr;
        if (gr < MROWS) {
            int b = (gr >= NTOT) ? 1 : 0;
            int n = gr - b * NTOT;
            if (n < NQ) Arow = X + (size_t)(b * NQ + n) * CC;
            else        Arow = S + (size_t)(b * NS + (n - NQ)) * CC;
        }
    }

    for (int k0 = 0; k0 < CC; k0 += 16) {
        {
            float4 a = make_float4(0.f, 0.f, 0.f, 0.f);
            if (Arow) a = *reinterpret_cast<const float4*>(Arow + k0 + lc4 * 4);
            As[lc4*4+0][lr] = a.x; As[lc4*4+1][lr] = a.y;
            As[lc4*4+2][lr] = a.z; As[lc4*4+3][lr] = a.w;
        }
        {
            float4 w = *reinterpret_cast<const float4*>(&W[(col0 + lr) * CC + k0 + lc4 * 4]);
            Ws[lc4*4+0][lr] = w.x; Ws[lc4*4+1][lr] = w.y;
            Ws[lc4*4+2][lr] = w.z; Ws[lc4*4+3][lr] = w.w;
        }
        __syncthreads();
        #pragma unroll
        for (int kk = 0; kk < 16; ++kk) {
            float4 a = *reinterpret_cast<const float4*>(&As[kk][ty * 4]);
            ulonglong2 w2 = *reinterpret_cast<const ulonglong2*>(&Ws[kk][tx * 4]);
            u64 a0 = pack2f(a.x, a.x);
            u64 a1 = pack2f(a.y, a.y);
            u64 a2 = pack2f(a.z, a.z);
            u64 a3 = pack2f(a.w, a.w);
            fma2(acc2[0][0], a0, w2.x); fma2(acc2[0][1], a0, w2.y);
            fma2(acc2[1][0], a1, w2.x); fma2(acc2[1][1], a1, w2.y);
            fma2(acc2[2][0], a2, w2.x); fma2(acc2[2][1], a2, w2.y);
            fma2(acc2[3][0], a3, w2.x); fma2(acc2[3][1], a3, w2.y);
        }
        __syncthreads();
    }

    #pragma unroll
    for (int i = 0; i < 4; i++) {
        int m = row0 + ty * 4 + i;
        if (m >= MROWS) continue;
        int b = (m >= NTOT) ? 1 : 0;
        int n = m - b * NTOT;
        #pragma unroll
        for (int j2 = 0; j2 < 4; j2 += 2) {
            int o = col0 + tx * 4 + j2;        // even
            float v0, v1;
            unpack2f(acc2[i][j2 >> 1], v0, v1);
            if (o < CC) {                       // Q: fold temp*log2e, split, packed
                int hh = o / DD, d = o % DD;    // d even
                float sc = T[hh] * LOG2E;
                float a0 = v0 * sc, a1 = v1 * sc;
                uint32_t hp = cvt_bf2(a1, a0);
                float r0 = a0 - __uint_as_float(hp << 16);
                float r1 = a1 - __uint_as_float(hp & 0xffff0000u);
                uint32_t lp = cvt_bf2(r1, r0);
                __nv_bfloat16* row = g_Qp + ((size_t)(b * HH + hh) * NKP + n) * QK_COLS;
                *reinterpret_cast<uint32_t*>(row + d)      = hp;   // qh
                *reinterpret_cast<uint32_t*>(row + 24 + d) = lp;   // ql
                *reinterpret_cast<uint32_t*>(row + 48 + d) = hp;   // qh dup
            } else if (o < 2 * CC) {            // K: split, packed
                int oo = o - CC, hh = oo / DD, d = oo % DD;
                uint32_t hp = cvt_bf2(v1, v0);
                float r0 = v0 - __uint_as_float(hp << 16);
                float r1 = v1 - __uint_as_float(hp & 0xffff0000u);
                uint32_t lp = cvt_bf2(r1, r0);
                __nv_bfloat16* row = g_Kp + ((size_t)(b * HH + hh) * NKP + n) * QK_COLS;
                *reinterpret_cast<uint32_t*>(row + d)      = hp;   // kh
                *reinterpret_cast<uint32_t*>(row + 24 + d) = hp;   // kh dup
                *reinterpret_cast<uint32_t*>(row + 48 + d) = lp;   // kl
            } else {                            // V: single fp16
                int oo = o - 2 * CC, hh = oo / DD, d = oo % DD;
                __half2 h2 = __floats2half2_rn(v0, v1);   // .x = v0 (low)
                __half* row = g_Vf + ((size_t)(b * HH + hh) * NKP + n) * V_COLS;
                *reinterpret_cast<uint32_t*>(row + d) = *reinterpret_cast<uint32_t*>(&h2);
            }
        }
    }
}

// ---------------------------------------------------------------------------
// 2) Attention: flash w/ online max, packed-K bf16 S-pass, fp16 PV pass.
//    256 threads, 128 queries (16 rows/warp), cp.async double buffering.
// smem layout (bytes):
//   0      : Q 128x176      22528
//   22528 + s*16384 (s=0,1):
//     +0      K 64x176       11264
//     +11264  V 64x80         5120
// total 55296
// ---------------------------------------------------------------------------
#define OQ  0
#define OKV 22528
#define STG 16384
#define OK_ 0
#define OV_ 11264
#define ATT_SMEM 55296

__global__ __launch_bounds__(256, 2)
void attn_kernel() {
    extern __shared__ __align__(16) uint8_t dsm[];
    const uint32_t sb = smem_u32(dsm);

    const int tid = threadIdx.x;
    const int w   = tid >> 5;
    const int t   = tid & 31;
    const int bh  = blockIdx.z * HH + blockIdx.y;
    const int q0  = blockIdx.x * 128;

    // ---- issue Q loads: 128 rows x 10 chunks(16B) = 1280 -> 5 per thread ----
    {
        int row = tid >> 1;
        const __nv_bfloat16* q = g_Qp + ((size_t)bh * NKP + q0 + row) * QK_COLS;
        uint32_t dst = sb + OQ + row * 176;
        #pragma unroll
        for (int u = 0; u < 5; u++) {
            int g = (tid & 1) * 5 + u;
            CP16(dst + g * 16, q + g * 8);
        }
    }
    // K/V loader: which = tid>>6: 0,1 -> K (64 rows x 10 chunks), 2 -> V (64x5)
    const int lwhich = tid >> 6;
    const int lrow   = tid & 63;
    {
        uint32_t kb = sb + OKV;
        if (lwhich < 2) {
            const __nv_bfloat16* src = g_Kp + ((size_t)bh * NKP + lrow) * QK_COLS;
            uint32_t dst = kb + OK_ + lrow * 176;
            #pragma unroll
            for (int u = 0; u < 5; u++) {
                int g = lwhich * 5 + u;
                CP16(dst + g * 16, src + g * 8);
            }
        } else if (lwhich == 2) {
            const __half* src = g_Vf + ((size_t)bh * NKP + lrow) * V_COLS;
            uint32_t dst = kb + OV_ + lrow * 80;
            #pragma unroll
            for (int u = 0; u < 5; u++) CP16(dst + u * 16, src + u * 8);
        }
    }
    CP_COMMIT();

    uint32_t aQ[5][4];         // [kstep][frag]
    float O[3][4];
    float lsum[2]   = {0.f, 0.f};
    float rowmax[2] = {-1e30f, -1e30f};
    #pragma unroll
    for (int nt = 0; nt < 3; nt++)
        #pragma unroll
        for (int c = 0; c < 4; c++) O[nt][c] = 0.f;

    for (int kt = 0; kt < KTILES; ++kt) {
        if (kt + 1 < KTILES) {
            const int j1 = (kt + 1) * 64;
            uint32_t kb = sb + OKV + ((kt + 1) & 1) * STG;
            if (lwhich < 2) {
                const __nv_bfloat16* src = g_Kp + ((size_t)bh * NKP + j1 + lrow) * QK_COLS;
                uint32_t dst = kb + OK_ + lrow * 176;
                #pragma unroll
                for (int u = 0; u < 5; u++) {
                    int g = lwhich * 5 + u;
                    CP16(dst + g * 16, src + g * 8);
                }
            } else if (lwhich == 2) {
                const __half* src = g_Vf + ((size_t)bh * NKP + j1 + lrow) * V_COLS;
                uint32_t dst = kb + OV_ + lrow * 80;
                #pragma unroll
                for (int u = 0; u < 5; u++) CP16(dst + u * 16, src + u * 8);
            }
            CP_COMMIT();
            CP_WAIT(1);
        } else {
            CP_WAIT(0);
        }
        __syncthreads();

        if (kt == 0) {
            // preload Q A-fragments (5 ksteps over 80 packed cols)
            int r = w * 16 + (t >> 2);
            const uint8_t* qr = dsm + OQ + r * 176;
            #pragma unroll
            for (int s = 0; s < 5; s++) {
                int off = s * 32 + (t & 3) * 4;
                aQ[s][0] = *reinterpret_cast<const uint32_t*>(qr + off);
                aQ[s][1] = *reinterpret_cast<const uint32_t*>(qr + 8 * 176 + off);
                aQ[s][2] = *reinterpret_cast<const uint32_t*>(qr + off + 16);
                aQ[s][3] = *reinterpret_cast<const uint32_t*>(qr + 8 * 176 + off + 16);
            }
        }

        const uint32_t kb = sb + OKV + (kt & 1) * STG;
        const int j0 = kt * 64;

        // ---- S: one packed K=80 GEMM (qh*kh + ql*kh + qh*kl) ----
        float C[8][4];
        #pragma unroll
        for (int nt = 0; nt < 8; nt++)
            #pragma unroll
            for (int c = 0; c < 4; c++) C[nt][c] = 0.f;

        const uint32_t krow_off = (uint32_t)(t & 7) * 176 + (((t >> 3) & 1) ? 16u : 0u);
        #pragma unroll
        for (int s = 0; s < 5; s++) {
            uint32_t b0[8], b1[8];
            #pragma unroll
            for (int nt = 0; nt < 8; nt++)
                ldsm_x2(b0[nt], b1[nt], kb + OK_ + (uint32_t)nt * 8 * 176 + s * 32 + krow_off);
            #pragma unroll
            for (int nt = 0; nt < 8; nt++)
                hmma_bf(C[nt], aQ[s][0], aQ[s][1], aQ[s][2], aQ[s][3], b0[nt], b1[nt]);
        }

        // ---- online max update ----
        float tm0 = C[0][0], tm1 = C[0][2];
        tm0 = fmaxf(tm0, C[0][1]); tm1 = fmaxf(tm1, C[0][3]);
        #pragma unroll
        for (int nt = 1; nt < 8; nt++) {
            tm0 = fmaxf(tm0, fmaxf(C[nt][0], C[nt][1]));
            tm1 = fmaxf(tm1, fmaxf(C[nt][2], C[nt][3]));
        }
        tm0 = fmaxf(tm0, __shfl_xor_sync(0xffffffffu, tm0, 1));
        tm0 = fmaxf(tm0, __shfl_xor_sync(0xffffffffu, tm0, 2));
        tm1 = fmaxf(tm1, __shfl_xor_sync(0xffffffffu, tm1, 1));
        tm1 = fmaxf(tm1, __shfl_xor_sync(0xffffffffu, tm1, 2));
        const float M0 = fmaxf(rowmax[0], tm0);
        const float M1 = fmaxf(rowmax[1], tm1);
        const float f0 = ex2f(rowmax[0] - M0);
        const float f1 = ex2f(rowmax[1] - M1);
        rowmax[0] = M0; rowmax[1] = M1;
        lsum[0] *= f0; lsum[1] *= f1;
        #pragma unroll
        for (int nt = 0; nt < 3; nt++) {
            O[nt][0] *= f0; O[nt][1] *= f0;
            O[nt][2] *= f1; O[nt][3] *= f1;
        }

        // ---- softmax: p = 2^(s - M) <= 1, pack fp16 pairs ----
        uint32_t PH[4][4];
        const bool edge = (j0 + 64 > NTOT);
        #pragma unroll
        for (int nt = 0; nt < 8; nt++) {
            float p0 = ex2f(C[nt][0] - M0);
            float p1 = ex2f(C[nt][1] - M0);
            float p2 = ex2f(C[nt][2] - M1);
            float p3 = ex2f(C[nt][3] - M1);
            if (edge) {
                int key0 = j0 + nt * 8 + (t & 3) * 2;
                if (key0     >= NTOT) { p0 = 0.f; p2 = 0.f; }
                if (key0 + 1 >= NTOT) { p1 = 0.f; p3 = 0.f; }
            }
            lsum[0] += p0 + p1;
            lsum[1] += p2 + p3;
            __half2 h01 = __floats2half2_rn(p0, p1);
            __half2 h23 = __floats2half2_rn(p2, p3);
            int ks = nt >> 1, half = nt & 1;
            PH[ks][half * 2 + 0] = *reinterpret_cast<uint32_t*>(&h01);
            PH[ks][half * 2 + 1] = *reinterpret_cast<uint32_t*>(&h23);
        }

        // ---- O += ph * v (fp16 single pass; V via ldmatrix.trans) ----
        const uint32_t vrow_off = (uint32_t)(t & 15) * 80;
        #pragma unroll
        for (int ks = 0; ks < 4; ks++) {
            #pragma unroll
            for (int nt = 0; nt < 3; nt++) {
                uint32_t v0, v1;
                ldsm_x2_t(v0, v1, kb + OV_ + (uint32_t)(ks * 16) * 80 + nt * 16 + vrow_off);
                hmma_f16(O[nt], PH[ks][0], PH[ks][1], PH[ks][2], PH[ks][3], v0, v1);
            }
        }
        __syncthreads();
    }

    // ---- reduce row sums over quad lanes, invert ----
    #pragma unroll
    for (int hf = 0; hf < 2; hf++) {
        float v = lsum[hf];
        v += __shfl_xor_sync(0xffffffffu, v, 1);
        v += __shfl_xor_sync(0xffffffffu, v, 2);
        lsum[hf] = 1.f / v;
    }

    // ---- epilogue: O / l -> g_O ----
    #pragma unroll
    for (int c = 0; c < 4; c++) {
        int row = w * 16 + (t >> 2) + ((c >> 1) ? 8 : 0);
        int q = q0 + row;
        if (q < NTOT) {
            float inv = lsum[c >> 1];
            #pragma unroll
            for (int nt = 0; nt < 3; nt++) {
                int d = blockIdx.y * DD + nt * 8 + (t & 3) * 2 + (c & 1);
                g_O[(size_t)(blockIdx.z * NTOT + q) * CC + d] = O[nt][c] * inv;
            }
        }
    }
}

// ---------------------------------------------------------------------------
// 3) Output projection: out[b,n,o] = sum_c O[b,n,c] * Wout[o,c], n < NQ only.
//    FFMA2 inner loop.
// ---------------------------------------------------------------------------
__global__ __launch_bounds__(256)
void out_gemm_kernel(const float* __restrict__ W, float* __restrict__ out) {
    __shared__ float As[16][64];
    __shared__ float Ws[16][64];

    const int tx = threadIdx.x;
    const int ty = threadIdx.y;
    const int t  = ty * 16 + tx;
    const int row0 = blockIdx.x * 64;
    const int col0 = blockIdx.y * 64;

    u64 acc2[4][2];
    #pragma unroll
    for (int i = 0; i < 4; i++) { acc2[i][0] = 0ull; acc2[i][1] = 0ull; }

    const int lr  = t >> 2;
    const int lc4 = t & 3;

    for (int k0 = 0; k0 < CC; k0 += 16) {
        {
            int m = row0 + lr;
            int b = m >> 12;
            int n = m & 4095;
            float4 a = *reinterpret_cast<const float4*>(
                &g_O[(size_t)(b * NTOT + n) * CC + k0 + lc4 * 4]);
            As[lc4*4+0][lr] = a.x; As[lc4*4+1][lr] = a.y;
            As[lc4*4+2][lr] = a.z; As[lc4*4+3][lr] = a.w;
        }
        {
            float4 w = *reinterpret_cast<const float4*>(&W[(col0 + lr) * CC + k0 + lc4 * 4]);
            Ws[lc4*4+0][lr] = w.x; Ws[lc4*4+1][lr] = w.y;
            Ws[lc4*4+2][lr] = w.z; Ws[lc4*4+3][lr] = w.w;
        }
        __syncthreads();
        #pragma unroll
        for (int kk = 0; kk < 16; ++kk) {
            float4 a = *reinterpret_cast<const float4*>(&As[kk][ty * 4]);
            ulonglong2 w2 = *reinterpret_cast<const ulonglong2*>(&Ws[kk][tx * 4]);
            u64 a0 = pack2f(a.x, a.x);
            u64 a1 = pack2f(a.y, a.y);
            u64 a2 = pack2f(a.z, a.z);
            u64 a3 = pack2f(a.w, a.w);
            fma2(acc2[0][0], a0, w2.x); fma2(acc2[0][1], a0, w2.y);
            fma2(acc2[1][0], a1, w2.x); fma2(acc2[1][1], a1, w2.y);
            fma2(acc2[2][0], a2, w2.x); fma2(acc2[2][1], a2, w2.y);
            fma2(acc2[3][0], a3, w2.x); fma2(acc2[3][1], a3, w2.y);
        }
        __syncthreads();
    }

    #pragma unroll
    for (int i = 0; i < 4; i++) {
        int m = row0 + ty * 4 + i;
        #pragma unroll
        for (int j2 = 0; j2 < 4; j2 += 2) {
            int o = col0 + tx * 4 + j2;
            float v0, v1;
            unpack2f(acc2[i][j2 >> 1], v0, v1);
            out[(size_t)m * CC + o]     = v0;
            out[(size_t)m * CC + o + 1] = v1;
        }
    }
}

// ---------------------------------------------------------------------------
// launch
// ---------------------------------------------------------------------------
extern "C" void kernel_launch(void* const* d_in, const int* in_sizes, int n_in,
                              void* d_out, int out_size) {
    const float* X  = nullptr;
    const float* S  = nullptr;
    const float* Wq = nullptr;
    const float* Wo = nullptr;
    const float* T  = nullptr;
    for (int i = 0; i < n_in; i++) {
        switch (in_sizes[i]) {
            case BB * NQ * CC:  X  = (const float*)d_in[i]; break;
            case BB * NS * CC:  S  = (const float*)d_in[i]; break;
            case 3 * CC * CC:   Wq = (const float*)d_in[i]; break;
            case CC * CC:       Wo = (const float*)d_in[i]; break;
            case HH:            T  = (const float*)d_in[i]; break;
        }
    }

    // 1) QKV projection (concat fused, packed split epilogue)
    {
        dim3 grid((MROWS + 63) / 64, (3 * CC) / 64);   // (129, 9)
        dim3 blk(16, 16);
        qkv_gemm_kernel<<<grid, blk>>>(X, S, Wq, T);
    }
    // 2) attention
    {
        cudaFuncSetAttribute(attn_kernel, cudaFuncAttributeMaxDynamicSharedMemorySize, ATT_SMEM);
        dim3 grid(QTILES, HH, BB);                      // (33, 8, 2)
        attn_kernel<<<grid, 256, ATT_SMEM>>>();
    }
    // 3) output projection
    {
        dim3 grid((BB * NQ) / 64, CC / 64);             // (128, 3)
        dim3 blk(16, 16);
        out_gemm_kernel<<<grid, blk>>>(Wo, (float*)d_out);
    }
}

// round 11
// speedup vs baseline: 1.1578x; 1.0795x over previous
#include <cuda_runtime.h>
#include <cuda_bf16.h>
#include <cuda_fp16.h>
#include <cstdint>

// Problem constants
#define BB    2
#define NQ    4096
#define NS    8
#define NTOT  4104          // NQ + NS
#define CC    192
#define HH    8
#define DD    24            // CC / HH
#define MROWS (BB*NTOT)     // 8208
#define NKP   4224          // padded to 33*128
#define QTILES 33           // q-tiles of 128
#define KTILES 65           // ceil(4104/64)
#define LOG2E 1.4426950408889634f

// packed row widths (elements)
#define QK_COLS 88          // 80 data cols (5 ksteps x16) + 8 pad; 176B rows
#define V_COLS  40          // fp16, 24 real + pad; 80B rows

typedef unsigned long long u64;

// ---------------------------------------------------------------------------
// helpers
// ---------------------------------------------------------------------------
__device__ __forceinline__ float ex2f(float x) {
    float r; asm("ex2.approx.f32 %0, %1;" : "=f"(r) : "f"(x)); return r;
}
__device__ __forceinline__ uint32_t cvt_bf2(float hi, float lo) {
    uint32_t r; asm("cvt.rn.bf16x2.f32 %0, %1, %2;" : "=r"(r) : "f"(hi), "f"(lo)); return r;
}
// bf16 mma
__device__ __forceinline__ void hmma_bf(float (&c)[4],
                                        uint32_t a0, uint32_t a1, uint32_t a2, uint32_t a3,
                                        uint32_t b0, uint32_t b1) {
    asm volatile(
        "mma.sync.aligned.m16n8k16.row.col.f32.bf16.bf16.f32 "
        "{%0,%1,%2,%3},{%4,%5,%6,%7},{%8,%9},{%0,%1,%2,%3};"
        : "+f"(c[0]), "+f"(c[1]), "+f"(c[2]), "+f"(c[3])
        : "r"(a0), "r"(a1), "r"(a2), "r"(a3), "r"(b0), "r"(b1));
}
// fp16 mma (PV pass)
__device__ __forceinline__ void hmma_f16(float (&c)[4],
                                         uint32_t a0, uint32_t a1, uint32_t a2, uint32_t a3,
                                         uint32_t b0, uint32_t b1) {
    asm volatile(
        "mma.sync.aligned.m16n8k16.row.col.f32.f16.f16.f32 "
        "{%0,%1,%2,%3},{%4,%5,%6,%7},{%8,%9},{%0,%1,%2,%3};"
        : "+f"(c[0]), "+f"(c[1]), "+f"(c[2]), "+f"(c[3])
        : "r"(a0), "r"(a1), "r"(a2), "r"(a3), "r"(b0), "r"(b1));
}
__device__ __forceinline__ uint32_t smem_u32(const void* p) {
    uint32_t a;
    asm("{ .reg .u64 t; cvta.to.shared.u64 t, %1; cvt.u32.u64 %0, t; }" : "=r"(a) : "l"(p));
    return a;
}
__device__ __forceinline__ void ldsm_x2(uint32_t& r0, uint32_t& r1, uint32_t addr) {
    asm volatile("ldmatrix.sync.aligned.m8n8.x2.shared.b16 {%0,%1}, [%2];"
                 : "=r"(r0), "=r"(r1) : "r"(addr));
}
__device__ __forceinline__ void ldsm_x4(uint32_t& r0, uint32_t& r1, uint32_t& r2, uint32_t& r3,
                                        uint32_t addr) {
    asm volatile("ldmatrix.sync.aligned.m8n8.x4.shared.b16 {%0,%1,%2,%3}, [%4];"
                 : "=r"(r0), "=r"(r1), "=r"(r2), "=r"(r3) : "r"(addr));
}
__device__ __forceinline__ void ldsm_x2_t(uint32_t& r0, uint32_t& r1, uint32_t addr) {
    asm volatile("ldmatrix.sync.aligned.m8n8.x2.trans.shared.b16 {%0,%1}, [%2];"
                 : "=r"(r0), "=r"(r1) : "r"(addr));
}
#define CP16(dst, src) \
    asm volatile("cp.async.cg.shared.global [%0], [%1], 16;" :: "r"(dst), "l"(src))
#define CP_COMMIT() asm volatile("cp.async.commit_group;" ::: "memory")
#define CP_WAIT(n)  asm volatile("cp.async.wait_group %0;" :: "n"(n) : "memory")

// ---------------------------------------------------------------------------
// Scratch (device globals; zero-initialized -> pad columns/rows stay 0)
// g_Qp rows: [qh(0:24) | ql(24:48) | qh(48:72) | 0(72:88)]   (bf16, temp*log2e folded)
// g_Kp rows: [kh(0:24) | kh(24:48) | kl(48:72) | 0(72:88)]   (bf16)
// g_Vf rows: [v(0:24) fp16 | 0]                               (fp16)
// ---------------------------------------------------------------------------
__device__ __align__(16) __nv_bfloat16 g_Qp[16*NKP*QK_COLS];
__device__ __align__(16) __nv_bfloat16 g_Kp[16*NKP*QK_COLS];
__device__ __align__(16) __half        g_Vf[16*NKP*V_COLS];
__device__ __align__(16) float g_O[BB*NTOT*CC];

// ---------------------------------------------------------------------------
// 1&3) Split-precision tensor GEMM: OUT[m,o] = sum_k A[m,k]*B[o,k] in
//      fp32-accurate 3-term bf16 (ah*bh + al*bh + ah*bl).
//      CTA: 128 threads (4 warps in 2x2), 64x64 tile, K in 6 chunks of 32.
//      MODE 0: A = concat(X,S); epilogue = Q/K/V split-pack (like R10).
//      MODE 1: A = g_O (rows b*4096+n); epilogue = plain store to out.
// ---------------------------------------------------------------------------
#define GK_CHUNKS 6         // 192 / 32
#define GSTRIDE   104       // packed row stride in bf16 elems (208 B)

template<int MODE>
__global__ __launch_bounds__(128)
void split_gemm_kernel(const float* __restrict__ X,
                       const float* __restrict__ S,
                       const float* __restrict__ B,
                       const float* __restrict__ T,
                       float* __restrict__ out) {
    __shared__ __align__(16) __nv_bfloat16 sA[64 * GSTRIDE];
    __shared__ __align__(16) __nv_bfloat16 sB[64 * GSTRIDE];

    const int tid = threadIdx.x;
    const int w   = tid >> 5;
    const int t   = tid & 31;
    const int mw  = w >> 1;            // 0,1 : m-half
    const int nw  = w & 1;             // 0,1 : n-half
    const int m0  = blockIdx.x * 64;
    const int n0  = blockIdx.y * 64;

    // staging mapping: thread stages row (tid>>1), 16 cols at (tid&1)*16
    const int srow = tid >> 1;
    const int scb  = tid & 1;

    // A source row pointer
    const float* Arow = nullptr;
    if (MODE == 0) {
        int gr = m0 + srow;
        if (gr < MROWS) {
            int b = (gr >= NTOT) ? 1 : 0;
            int n = gr - b * NTOT;
            if (n < NQ) Arow = X + (size_t)(b * NQ + n) * CC;
            else        Arow = S + (size_t)(b * NS + (n - NQ)) * CC;
        }
    } else {
        int gr = m0 + srow;            // 0..8191
        int b = gr >> 12;
        int n = gr & 4095;
        Arow = g_O + (size_t)(b * NTOT + n) * CC;
    }
    const float* Brow = B + (size_t)(n0 + srow) * CC;

    float av[16], bv[16];
    // preload chunk 0
    {
        #pragma unroll
        for (int q = 0; q < 4; q++) {
            float4 x = Arow ? *reinterpret_cast<const float4*>(Arow + scb * 16 + q * 4)
                            : make_float4(0.f, 0.f, 0.f, 0.f);
            av[q*4+0]=x.x; av[q*4+1]=x.y; av[q*4+2]=x.z; av[q*4+3]=x.w;
            float4 y = *reinterpret_cast<const float4*>(Brow + scb * 16 + q * 4);
            bv[q*4+0]=y.x; bv[q*4+1]=y.y; bv[q*4+2]=y.z; bv[q*4+3]=y.w;
        }
    }

    float C[2][4][4];
    #pragma unroll
    for (int mt = 0; mt < 2; mt++)
        #pragma unroll
        for (int nt = 0; nt < 4; nt++)
            #pragma unroll
            for (int c = 0; c < 4; c++) C[mt][nt][c] = 0.f;

    const uint32_t sAb = smem_u32(sA);
    const uint32_t sBb = smem_u32(sB);

    for (int kc = 0; kc < GK_CHUNKS; kc++) {
        // ---- pack staged regs -> smem: A [ah|al|ah], B [bh|bh|bl] ----
        {
            uint32_t ah[8], al[8], bh[8], bl[8];
            #pragma unroll
            for (int i = 0; i < 8; i++) {
                float a0 = av[2*i], a1 = av[2*i+1];
                uint32_t hp = cvt_bf2(a1, a0);
                float r0 = a0 - __uint_as_float(hp << 16);
                float r1 = a1 - __uint_as_float(hp & 0xffff0000u);
                ah[i] = hp; al[i] = cvt_bf2(r1, r0);
                float b0 = bv[2*i], b1 = bv[2*i+1];
                uint32_t hq = cvt_bf2(b1, b0);
                float s0 = b0 - __uint_as_float(hq << 16);
                float s1 = b1 - __uint_as_float(hq & 0xffff0000u);
                bh[i] = hq; bl[i] = cvt_bf2(s1, s0);
            }
            __nv_bfloat16* ar = sA + srow * GSTRIDE + scb * 16;
            __nv_bfloat16* br = sB + srow * GSTRIDE + scb * 16;
            *reinterpret_cast<uint4*>(ar)          = make_uint4(ah[0],ah[1],ah[2],ah[3]);
            *reinterpret_cast<uint4*>(ar + 8)      = make_uint4(ah[4],ah[5],ah[6],ah[7]);
            *reinterpret_cast<uint4*>(ar + 32)     = make_uint4(al[0],al[1],al[2],al[3]);
            *reinterpret_cast<uint4*>(ar + 40)     = make_uint4(al[4],al[5],al[6],al[7]);
            *reinterpret_cast<uint4*>(ar + 64)     = make_uint4(ah[0],ah[1],ah[2],ah[3]);
            *reinterpret_cast<uint4*>(ar + 72)     = make_uint4(ah[4],ah[5],ah[6],ah[7]);
            *reinterpret_cast<uint4*>(br)          = make_uint4(bh[0],bh[1],bh[2],bh[3]);
            *reinterpret_cast<uint4*>(br + 8)      = make_uint4(bh[4],bh[5],bh[6],bh[7]);
            *reinterpret_cast<uint4*>(br + 32)     = make_uint4(bh[0],bh[1],bh[2],bh[3]);
            *reinterpret_cast<uint4*>(br + 40)     = make_uint4(bh[4],bh[5],bh[6],bh[7]);
            *reinterpret_cast<uint4*>(br + 64)     = make_uint4(bl[0],bl[1],bl[2],bl[3]);
            *reinterpret_cast<uint4*>(br + 72)     = make_uint4(bl[4],bl[5],bl[6],bl[7]);
        }
        __syncthreads();

        // ---- stage next chunk (hidden under MMAs) ----
        if (kc + 1 < GK_CHUNKS) {
            int k0 = (kc + 1) * 32 + scb * 16;
            #pragma unroll
            for (int q = 0; q < 4; q++) {
                float4 x = Arow ? *reinterpret_cast<const float4*>(Arow + k0 + q * 4)
                                : make_float4(0.f, 0.f, 0.f, 0.f);
                av[q*4+0]=x.x; av[q*4+1]=x.y; av[q*4+2]=x.z; av[q*4+3]=x.w;
                float4 y = *reinterpret_cast<const float4*>(Brow + k0 + q * 4);
                bv[q*4+0]=y.x; bv[q*4+1]=y.y; bv[q*4+2]=y.z; bv[q*4+3]=y.w;
            }
        }

        // ---- MMAs: 6 ksteps over packed 96 cols ----
        #pragma unroll
        for (int s = 0; s < 6; s++) {
            uint32_t aA[2][4];
            #pragma unroll
            for (int mt = 0; mt < 2; mt++)
                ldsm_x4(aA[mt][0], aA[mt][1], aA[mt][2], aA[mt][3],
                        sAb + (uint32_t)(mw*32 + mt*16 + (t & 15)) * (GSTRIDE*2)
                            + ((t >> 4) & 1) * 16 + s * 32);
            uint32_t bB[4][2];
            #pragma unroll
            for (int nt = 0; nt < 4; nt++)
                ldsm_x2(bB[nt][0], bB[nt][1],
                        sBb + (uint32_t)(nw*32 + nt*8 + (t & 7)) * (GSTRIDE*2)
                            + ((t >> 3) & 1) * 16 + s * 32);
            #pragma unroll
            for (int mt = 0; mt < 2; mt++)
                #pragma unroll
                for (int nt = 0; nt < 4; nt++)
                    hmma_bf(C[mt][nt], aA[mt][0], aA[mt][1], aA[mt][2], aA[mt][3],
                            bB[nt][0], bB[nt][1]);
        }
        __syncthreads();
    }

    // ---- epilogue ----
    #pragma unroll
    for (int mt = 0; mt < 2; mt++) {
        #pragma unroll
        for (int cp = 0; cp < 2; cp++) {
            int row = m0 + mw * 32 + mt * 16 + (t >> 2) + cp * 8;
            if (MODE == 0 && row >= MROWS) continue;
            int b, n;
            if (MODE == 0) { b = (row >= NTOT) ? 1 : 0; n = row - b * NTOT; }
            #pragma unroll
            for (int nt = 0; nt < 4; nt++) {
                int o = n0 + nw * 32 + nt * 8 + (t & 3) * 2;   // even
                float v0 = C[mt][nt][cp * 2];
                float v1 = C[mt][nt][cp * 2 + 1];
                if (MODE == 1) {
                    out[(size_t)row * CC + o]     = v0;
                    out[(size_t)row * CC + o + 1] = v1;
                } else {
                    if (o < CC) {                       // Q: fold temp*log2e, split, packed
                        int hh = o / DD, d = o % DD;
                        float sc = T[hh] * LOG2E;
                        float a0 = v0 * sc, a1 = v1 * sc;
                        uint32_t hp = cvt_bf2(a1, a0);
                        float r0 = a0 - __uint_as_float(hp << 16);
                        float r1 = a1 - __uint_as_float(hp & 0xffff0000u);
                        uint32_t lp = cvt_bf2(r1, r0);
                        __nv_bfloat16* rw = g_Qp + ((size_t)(b * HH + hh) * NKP + n) * QK_COLS;
                        *reinterpret_cast<uint32_t*>(rw + d)      = hp;
                        *reinterpret_cast<uint32_t*>(rw + 24 + d) = lp;
                        *reinterpret_cast<uint32_t*>(rw + 48 + d) = hp;
                    } else if (o < 2 * CC) {            // K
                        int oo = o - CC, hh = oo / DD, d = oo % DD;
                        uint32_t hp = cvt_bf2(v1, v0);
                        float r0 = v0 - __uint_as_float(hp << 16);
                        float r1 = v1 - __uint_as_float(hp & 0xffff0000u);
                        uint32_t lp = cvt_bf2(r1, r0);
                        __nv_bfloat16* rw = g_Kp + ((size_t)(b * HH + hh) * NKP + n) * QK_COLS;
                        *reinterpret_cast<uint32_t*>(rw + d)      = hp;
                        *reinterpret_cast<uint32_t*>(rw + 24 + d) = hp;
                        *reinterpret_cast<uint32_t*>(rw + 48 + d) = lp;
                    } else {                            // V: single fp16
                        int oo = o - 2 * CC, hh = oo / DD, d = oo % DD;
                        __half2 h2 = __floats2half2_rn(v0, v1);
                        __half* rw = g_Vf + ((size_t)(b * HH + hh) * NKP + n) * V_COLS;
                        *reinterpret_cast<uint32_t*>(rw + d) = *reinterpret_cast<uint32_t*>(&h2);
                    }
                }
            }
        }
    }
}

// ---------------------------------------------------------------------------
// 2) Attention: flash w/ online max, packed-K bf16 S-pass, fp16 PV pass.
//    (unchanged from R10)
// ---------------------------------------------------------------------------
#define OQ  0
#define OKV 22528
#define STG 16384
#define OK_ 0
#define OV_ 11264
#define ATT_SMEM 55296

__global__ __launch_bounds__(256, 2)
void attn_kernel() {
    extern __shared__ __align__(16) uint8_t dsm[];
    const uint32_t sb = smem_u32(dsm);

    const int tid = threadIdx.x;
    const int w   = tid >> 5;
    const int t   = tid & 31;
    const int bh  = blockIdx.z * HH + blockIdx.y;
    const int q0  = blockIdx.x * 128;

    {
        int row = tid >> 1;
        const __nv_bfloat16* q = g_Qp + ((size_t)bh * NKP + q0 + row) * QK_COLS;
        uint32_t dst = sb + OQ + row * 176;
        #pragma unroll
        for (int u = 0; u < 5; u++) {
            int g = (tid & 1) * 5 + u;
            CP16(dst + g * 16, q + g * 8);
        }
    }
    const int lwhich = tid >> 6;
    const int lrow   = tid & 63;
    {
        uint32_t kb = sb + OKV;
        if (lwhich < 2) {
            const __nv_bfloat16* src = g_Kp + ((size_t)bh * NKP + lrow) * QK_COLS;
            uint32_t dst = kb + OK_ + lrow * 176;
            #pragma unroll
            for (int u = 0; u < 5; u++) {
                int g = lwhich * 5 + u;
                CP16(dst + g * 16, src + g * 8);
            }
        } else if (lwhich == 2) {
            const __half* src = g_Vf + ((size_t)bh * NKP + lrow) * V_COLS;
            uint32_t dst = kb + OV_ + lrow * 80;
            #pragma unroll
            for (int u = 0; u < 5; u++) CP16(dst + u * 16, src + u * 8);
        }
    }
    CP_COMMIT();

    uint32_t aQ[5][4];
    float O[3][4];
    float lsum[2]   = {0.f, 0.f};
    float rowmax[2] = {-1e30f, -1e30f};
    #pragma unroll
    for (int nt = 0; nt < 3; nt++)
        #pragma unroll
        for (int c = 0; c < 4; c++) O[nt][c] = 0.f;

    for (int kt = 0; kt < KTILES; ++kt) {
        if (kt + 1 < KTILES) {
            const int j1 = (kt + 1) * 64;
            uint32_t kb = sb + OKV + ((kt + 1) & 1) * STG;
            if (lwhich < 2) {
                const __nv_bfloat16* src = g_Kp + ((size_t)bh * NKP + j1 + lrow) * QK_COLS;
                uint32_t dst = kb + OK_ + lrow * 176;
                #pragma unroll
                for (int u = 0; u < 5; u++) {
                    int g = lwhich * 5 + u;
                    CP16(dst + g * 16, src + g * 8);
                }
            } else if (lwhich == 2) {
                const __half* src = g_Vf + ((size_t)bh * NKP + j1 + lrow) * V_COLS;
                uint32_t dst = kb + OV_ + lrow * 80;
                #pragma unroll
                for (int u = 0; u < 5; u++) CP16(dst + u * 16, src + u * 8);
            }
            CP_COMMIT();
            CP_WAIT(1);
        } else {
            CP_WAIT(0);
        }
        __syncthreads();

        if (kt == 0) {
            int r = w * 16 + (t >> 2);
            const uint8_t* qr = dsm + OQ + r * 176;
            #pragma unroll
            for (int s = 0; s < 5; s++) {
                int off = s * 32 + (t & 3) * 4;
                aQ[s][0] = *reinterpret_cast<const uint32_t*>(qr + off);
                aQ[s][1] = *reinterpret_cast<const uint32_t*>(qr + 8 * 176 + off);
                aQ[s][2] = *reinterpret_cast<const uint32_t*>(qr + off + 16);
                aQ[s][3] = *reinterpret_cast<const uint32_t*>(qr + 8 * 176 + off + 16);
            }
        }

        const uint32_t kb = sb + OKV + (kt & 1) * STG;
        const int j0 = kt * 64;

        float C[8][4];
        #pragma unroll
        for (int nt = 0; nt < 8; nt++)
            #pragma unroll
            for (int c = 0; c < 4; c++) C[nt][c] = 0.f;

        const uint32_t krow_off = (uint32_t)(t & 7) * 176 + (((t >> 3) & 1) ? 16u : 0u);
        #pragma unroll
        for (int s = 0; s < 5; s++) {
            uint32_t b0[8], b1[8];
            #pragma unroll
            for (int nt = 0; nt < 8; nt++)
                ldsm_x2(b0[nt], b1[nt], kb + OK_ + (uint32_t)nt * 8 * 176 + s * 32 + krow_off);
            #pragma unroll
            for (int nt = 0; nt < 8; nt++)
                hmma_bf(C[nt], aQ[s][0], aQ[s][1], aQ[s][2], aQ[s][3], b0[nt], b1[nt]);
        }

        float tm0 = C[0][0], tm1 = C[0][2];
        tm0 = fmaxf(tm0, C[0][1]); tm1 = fmaxf(tm1, C[0][3]);
        #pragma unroll
        for (int nt = 1; nt < 8; nt++) {
            tm0 = fmaxf(tm0, fmaxf(C[nt][0], C[nt][1]));
            tm1 = fmaxf(tm1, fmaxf(C[nt][2], C[nt][3]));
        }
        tm0 = fmaxf(tm0, __shfl_xor_sync(0xffffffffu, tm0, 1));
        tm0 = fmaxf(tm0, __shfl_xor_sync(0xffffffffu, tm0, 2));
        tm1 = fmaxf(tm1, __shfl_xor_sync(0xffffffffu, tm1, 1));
        tm1 = fmaxf(tm1, __shfl_xor_sync(0xffffffffu, tm1, 2));
        const float M0 = fmaxf(rowmax[0], tm0);
        const float M1 = fmaxf(rowmax[1], tm1);
        const float f0 = ex2f(rowmax[0] - M0);
        const float f1 = ex2f(rowmax[1] - M1);
        rowmax[0] = M0; rowmax[1] = M1;
        lsum[0] *= f0; lsum[1] *= f1;
        #pragma unroll
        for (int nt = 0; nt < 3; nt++) {
            O[nt][0] *= f0; O[nt][1] *= f0;
            O[nt][2] *= f1; O[nt][3] *= f1;
        }

        uint32_t PH[4][4];
        const bool edge = (j0 + 64 > NTOT);
        #pragma unroll
        for (int nt = 0; nt < 8; nt++) {
            float p0 = ex2f(C[nt][0] - M0);
            float p1 = ex2f(C[nt][1] - M0);
            float p2 = ex2f(C[nt][2] - M1);
            float p3 = ex2f(C[nt][3] - M1);
            if (edge) {
                int key0 = j0 + nt * 8 + (t & 3) * 2;
                if (key0     >= NTOT) { p0 = 0.f; p2 = 0.f; }
                if (key0 + 1 >= NTOT) { p1 = 0.f; p3 = 0.f; }
            }
            lsum[0] += p0 + p1;
            lsum[1] += p2 + p3;
            __half2 h01 = __floats2half2_rn(p0, p1);
            __half2 h23 = __floats2half2_rn(p2, p3);
            int ks = nt >> 1, half = nt & 1;
            PH[ks][half * 2 + 0] = *reinterpret_cast<uint32_t*>(&h01);
            PH[ks][half * 2 + 1] = *reinterpret_cast<uint32_t*>(&h23);
        }

        const uint32_t vrow_off = (uint32_t)(t & 15) * 80;
        #pragma unroll
        for (int ks = 0; ks < 4; ks++) {
            #pragma unroll
            for (int nt = 0; nt < 3; nt++) {
                uint32_t v0, v1;
                ldsm_x2_t(v0, v1, kb + OV_ + (uint32_t)(ks * 16) * 80 + nt * 16 + vrow_off);
                hmma_f16(O[nt], PH[ks][0], PH[ks][1], PH[ks][2], PH[ks][3], v0, v1);
            }
        }
        __syncthreads();
    }

    #pragma unroll
    for (int hf = 0; hf < 2; hf++) {
        float v = lsum[hf];
        v += __shfl_xor_sync(0xffffffffu, v, 1);
        v += __shfl_xor_sync(0xffffffffu, v, 2);
        lsum[hf] = 1.f / v;
    }

    #pragma unroll
    for (int c = 0; c < 4; c++) {
        int row = w * 16 + (t >> 2) + ((c >> 1) ? 8 : 0);
        int q = q0 + row;
        if (q < NTOT) {
            float inv = lsum[c >> 1];
            #pragma unroll
            for (int nt = 0; nt < 3; nt++) {
                int d = blockIdx.y * DD + nt * 8 + (t & 3) * 2 + (c & 1);
                g_O[(size_t)(blockIdx.z * NTOT + q) * CC + d] = O[nt][c] * inv;
            }
        }
    }
}

// ---------------------------------------------------------------------------
// launch
// ---------------------------------------------------------------------------
extern "C" void kernel_launch(void* const* d_in, const int* in_sizes, int n_in,
                              void* d_out, int out_size) {
    const float* X  = nullptr;
    const float* S  = nullptr;
    const float* Wq = nullptr;
    const float* Wo = nullptr;
    const float* T  = nullptr;
    for (int i = 0; i < n_in; i++) {
        switch (in_sizes[i]) {
            case BB * NQ * CC:  X  = (const float*)d_in[i]; break;
            case BB * NS * CC:  S  = (const float*)d_in[i]; break;
            case 3 * CC * CC:   Wq = (const float*)d_in[i]; break;
            case CC * CC:       Wo = (const float*)d_in[i]; break;
            case HH:            T  = (const float*)d_in[i]; break;
        }
    }

    // 1) QKV projection (split tensor GEMM, concat fused, packed epilogue)
    {
        dim3 grid((MROWS + 63) / 64, (3 * CC) / 64);   // (129, 9)
        split_gemm_kernel<0><<<grid, 128>>>(X, S, Wq, T, nullptr);
    }
    // 2) attention
    {
        cudaFuncSetAttribute(attn_kernel, cudaFuncAttributeMaxDynamicSharedMemorySize, ATT_SMEM);
        dim3 grid(QTILES, HH, BB);                      // (33, 8, 2)
        attn_kernel<<<grid, 256, ATT_SMEM>>>();
    }
    // 3) output projection (split tensor GEMM)
    {
        dim3 grid((BB * NQ) / 64, CC / 64);             // (128, 3)
        split_gemm_kernel<1><<<grid, 128>>>(nullptr, nullptr, Wo, nullptr, (float*)d_out);
    }
}

// round 12
// speedup vs baseline: 1.2752x; 1.1014x over previous
#include <cuda_runtime.h>
#include <cuda_bf16.h>
#include <cuda_fp16.h>
#include <cstdint>

// Problem constants
#define BB    2
#define NQ    4096
#define NS    8
#define NTOT  4104          // NQ + NS
#define CC    192
#define HH    8
#define DD    24            // CC / HH
#define MROWS (BB*NTOT)     // 8208
#define NKP   4352          // padded to 17*256 (query tiles of 256)
#define QTILES 17           // q-tiles of 256
#define KTILES 65           // ceil(4104/64)
#define LOG2E 1.4426950408889634f

// packed row widths (elements)
#define QK_COLS 88          // 80 data cols (5 ksteps x16) + 8 pad; 176B rows
#define V_COLS  40          // fp16, 24 real + pad; 80B rows

typedef unsigned long long u64;

// ---------------------------------------------------------------------------
// helpers
// ---------------------------------------------------------------------------
__device__ __forceinline__ float ex2f(float x) {
    float r; asm("ex2.approx.f32 %0, %1;" : "=f"(r) : "f"(x)); return r;
}
__device__ __forceinline__ uint32_t cvt_bf2(float hi, float lo) {
    uint32_t r; asm("cvt.rn.bf16x2.f32 %0, %1, %2;" : "=r"(r) : "f"(hi), "f"(lo)); return r;
}
// bf16 mma
__device__ __forceinline__ void hmma_bf(float (&c)[4],
                                        uint32_t a0, uint32_t a1, uint32_t a2, uint32_t a3,
                                        uint32_t b0, uint32_t b1) {
    asm volatile(
        "mma.sync.aligned.m16n8k16.row.col.f32.bf16.bf16.f32 "
        "{%0,%1,%2,%3},{%4,%5,%6,%7},{%8,%9},{%0,%1,%2,%3};"
        : "+f"(c[0]), "+f"(c[1]), "+f"(c[2]), "+f"(c[3])
        : "r"(a0), "r"(a1), "r"(a2), "r"(a3), "r"(b0), "r"(b1));
}
// fp16 mma (PV pass)
__device__ __forceinline__ void hmma_f16(float (&c)[4],
                                         uint32_t a0, uint32_t a1, uint32_t a2, uint32_t a3,
                                         uint32_t b0, uint32_t b1) {
    asm volatile(
        "mma.sync.aligned.m16n8k16.row.col.f32.f16.f16.f32 "
        "{%0,%1,%2,%3},{%4,%5,%6,%7},{%8,%9},{%0,%1,%2,%3};"
        : "+f"(c[0]), "+f"(c[1]), "+f"(c[2]), "+f"(c[3])
        : "r"(a0), "r"(a1), "r"(a2), "r"(a3), "r"(b0), "r"(b1));
}
__device__ __forceinline__ uint32_t smem_u32(const void* p) {
    uint32_t a;
    asm("{ .reg .u64 t; cvta.to.shared.u64 t, %1; cvt.u32.u64 %0, t; }" : "=r"(a) : "l"(p));
    return a;
}
__device__ __forceinline__ void ldsm_x2(uint32_t& r0, uint32_t& r1, uint32_t addr) {
    asm volatile("ldmatrix.sync.aligned.m8n8.x2.shared.b16 {%0,%1}, [%2];"
                 : "=r"(r0), "=r"(r1) : "r"(addr));
}
__device__ __forceinline__ void ldsm_x4(uint32_t& r0, uint32_t& r1, uint32_t& r2, uint32_t& r3,
                                        uint32_t addr) {
    asm volatile("ldmatrix.sync.aligned.m8n8.x4.shared.b16 {%0,%1,%2,%3}, [%4];"
                 : "=r"(r0), "=r"(r1), "=r"(r2), "=r"(r3) : "r"(addr));
}
__device__ __forceinline__ void ldsm_x2_t(uint32_t& r0, uint32_t& r1, uint32_t addr) {
    asm volatile("ldmatrix.sync.aligned.m8n8.x2.trans.shared.b16 {%0,%1}, [%2];"
                 : "=r"(r0), "=r"(r1) : "r"(addr));
}
#define CP16(dst, src) \
    asm volatile("cp.async.cg.shared.global [%0], [%1], 16;" :: "r"(dst), "l"(src))
#define CP_COMMIT() asm volatile("cp.async.commit_group;" ::: "memory")
#define CP_WAIT(n)  asm volatile("cp.async.wait_group %0;" :: "n"(n) : "memory")

// ---------------------------------------------------------------------------
// Scratch (device globals; zero-initialized -> pad columns/rows stay 0)
// g_Qp rows: [qh(0:24) | ql(24:48) | qh(48:72) | 0(72:88)]   (bf16, temp*log2e folded)
// g_Kp rows: [kh(0:24) | kh(24:48) | kl(48:72) | 0(72:88)]   (bf16)
// g_Vf rows: [v(0:24) fp16 | 0]                               (fp16)
// ---------------------------------------------------------------------------
__device__ __align__(16) __nv_bfloat16 g_Qp[16*NKP*QK_COLS];
__device__ __align__(16) __nv_bfloat16 g_Kp[16*NKP*QK_COLS];
__device__ __align__(16) __half        g_Vf[16*NKP*V_COLS];
__device__ __align__(16) float g_O[BB*NTOT*CC];

// ---------------------------------------------------------------------------
// 1&3) Split-precision tensor GEMM (unchanged from R11).
// ---------------------------------------------------------------------------
#define GK_CHUNKS 6         // 192 / 32
#define GSTRIDE   104       // packed row stride in bf16 elems (208 B)

template<int MODE>
__global__ __launch_bounds__(128)
void split_gemm_kernel(const float* __restrict__ X,
                       const float* __restrict__ S,
                       const float* __restrict__ B,
                       const float* __restrict__ T,
                       float* __restrict__ out) {
    __shared__ __align__(16) __nv_bfloat16 sA[64 * GSTRIDE];
    __shared__ __align__(16) __nv_bfloat16 sB[64 * GSTRIDE];

    const int tid = threadIdx.x;
    const int w   = tid >> 5;
    const int t   = tid & 31;
    const int mw  = w >> 1;
    const int nw  = w & 1;
    const int m0  = blockIdx.x * 64;
    const int n0  = blockIdx.y * 64;

    const int srow = tid >> 1;
    const int scb  = tid & 1;

    const float* Arow = nullptr;
    if (MODE == 0) {
        int gr = m0 + srow;
        if (gr < MROWS) {
            int b = (gr >= NTOT) ? 1 : 0;
            int n = gr - b * NTOT;
            if (n < NQ) Arow = X + (size_t)(b * NQ + n) * CC;
            else        Arow = S + (size_t)(b * NS + (n - NQ)) * CC;
        }
    } else {
        int gr = m0 + srow;
        int b = gr >> 12;
        int n = gr & 4095;
        Arow = g_O + (size_t)(b * NTOT + n) * CC;
    }
    const float* Brow = B + (size_t)(n0 + srow) * CC;

    float av[16], bv[16];
    {
        #pragma unroll
        for (int q = 0; q < 4; q++) {
            float4 x = Arow ? *reinterpret_cast<const float4*>(Arow + scb * 16 + q * 4)
                            : make_float4(0.f, 0.f, 0.f, 0.f);
            av[q*4+0]=x.x; av[q*4+1]=x.y; av[q*4+2]=x.z; av[q*4+3]=x.w;
            float4 y = *reinterpret_cast<const float4*>(Brow + scb * 16 + q * 4);
            bv[q*4+0]=y.x; bv[q*4+1]=y.y; bv[q*4+2]=y.z; bv[q*4+3]=y.w;
        }
    }

    float C[2][4][4];
    #pragma unroll
    for (int mt = 0; mt < 2; mt++)
        #pragma unroll
        for (int nt = 0; nt < 4; nt++)
            #pragma unroll
            for (int c = 0; c < 4; c++) C[mt][nt][c] = 0.f;

    const uint32_t sAb = smem_u32(sA);
    const uint32_t sBb = smem_u32(sB);

    for (int kc = 0; kc < GK_CHUNKS; kc++) {
        {
            uint32_t ah[8], al[8], bh[8], bl[8];
            #pragma unroll
            for (int i = 0; i < 8; i++) {
                float a0 = av[2*i], a1 = av[2*i+1];
                uint32_t hp = cvt_bf2(a1, a0);
                float r0 = a0 - __uint_as_float(hp << 16);
                float r1 = a1 - __uint_as_float(hp & 0xffff0000u);
                ah[i] = hp; al[i] = cvt_bf2(r1, r0);
                float b0 = bv[2*i], b1 = bv[2*i+1];
                uint32_t hq = cvt_bf2(b1, b0);
                float s0 = b0 - __uint_as_float(hq << 16);
                float s1 = b1 - __uint_as_float(hq & 0xffff0000u);
                bh[i] = hq; bl[i] = cvt_bf2(s1, s0);
            }
            __nv_bfloat16* ar = sA + srow * GSTRIDE + scb * 16;
            __nv_bfloat16* br = sB + srow * GSTRIDE + scb * 16;
            *reinterpret_cast<uint4*>(ar)          = make_uint4(ah[0],ah[1],ah[2],ah[3]);
            *reinterpret_cast<uint4*>(ar + 8)      = make_uint4(ah[4],ah[5],ah[6],ah[7]);
            *reinterpret_cast<uint4*>(ar + 32)     = make_uint4(al[0],al[1],al[2],al[3]);
            *reinterpret_cast<uint4*>(ar + 40)     = make_uint4(al[4],al[5],al[6],al[7]);
            *reinterpret_cast<uint4*>(ar + 64)     = make_uint4(ah[0],ah[1],ah[2],ah[3]);
            *reinterpret_cast<uint4*>(ar + 72)     = make_uint4(ah[4],ah[5],ah[6],ah[7]);
            *reinterpret_cast<uint4*>(br)          = make_uint4(bh[0],bh[1],bh[2],bh[3]);
            *reinterpret_cast<uint4*>(br + 8)      = make_uint4(bh[4],bh[5],bh[6],bh[7]);
            *reinterpret_cast<uint4*>(br + 32)     = make_uint4(bh[0],bh[1],bh[2],bh[3]);
            *reinterpret_cast<uint4*>(br + 40)     = make_uint4(bh[4],bh[5],bh[6],bh[7]);
            *reinterpret_cast<uint4*>(br + 64)     = make_uint4(bl[0],bl[1],bl[2],bl[3]);
            *reinterpret_cast<uint4*>(br + 72)     = make_uint4(bl[4],bl[5],bl[6],bl[7]);
        }
        __syncthreads();

        if (kc + 1 < GK_CHUNKS) {
            int k0 = (kc + 1) * 32 + scb * 16;
            #pragma unroll
            for (int q = 0; q < 4; q++) {
                float4 x = Arow ? *reinterpret_cast<const float4*>(Arow + k0 + q * 4)
                                : make_float4(0.f, 0.f, 0.f, 0.f);
                av[q*4+0]=x.x; av[q*4+1]=x.y; av[q*4+2]=x.z; av[q*4+3]=x.w;
                float4 y = *reinterpret_cast<const float4*>(Brow + k0 + q * 4);
                bv[q*4+0]=y.x; bv[q*4+1]=y.y; bv[q*4+2]=y.z; bv[q*4+3]=y.w;
            }
        }

        #pragma unroll
        for (int s = 0; s < 6; s++) {
            uint32_t aA[2][4];
            #pragma unroll
            for (int mt = 0; mt < 2; mt++)
                ldsm_x4(aA[mt][0], aA[mt][1], aA[mt][2], aA[mt][3],
                        sAb + (uint32_t)(mw*32 + mt*16 + (t & 15)) * (GSTRIDE*2)
                            + ((t >> 4) & 1) * 16 + s * 32);
            uint32_t bB[4][2];
            #pragma unroll
            for (int nt = 0; nt < 4; nt++)
                ldsm_x2(bB[nt][0], bB[nt][1],
                        sBb + (uint32_t)(nw*32 + nt*8 + (t & 7)) * (GSTRIDE*2)
                            + ((t >> 3) & 1) * 16 + s * 32);
            #pragma unroll
            for (int mt = 0; mt < 2; mt++)
                #pragma unroll
                for (int nt = 0; nt < 4; nt++)
                    hmma_bf(C[mt][nt], aA[mt][0], aA[mt][1], aA[mt][2], aA[mt][3],
                            bB[nt][0], bB[nt][1]);
        }
        __syncthreads();
    }

    #pragma unroll
    for (int mt = 0; mt < 2; mt++) {
        #pragma unroll
        for (int cp = 0; cp < 2; cp++) {
            int row = m0 + mw * 32 + mt * 16 + (t >> 2) + cp * 8;
            if (MODE == 0 && row >= MROWS) continue;
            int b, n;
            if (MODE == 0) { b = (row >= NTOT) ? 1 : 0; n = row - b * NTOT; }
            #pragma unroll
            for (int nt = 0; nt < 4; nt++) {
                int o = n0 + nw * 32 + nt * 8 + (t & 3) * 2;
                float v0 = C[mt][nt][cp * 2];
                float v1 = C[mt][nt][cp * 2 + 1];
                if (MODE == 1) {
                    out[(size_t)row * CC + o]     = v0;
                    out[(size_t)row * CC + o + 1] = v1;
                } else {
                    if (o < CC) {
                        int hh = o / DD, d = o % DD;
                        float sc = T[hh] * LOG2E;
                        float a0 = v0 * sc, a1 = v1 * sc;
                        uint32_t hp = cvt_bf2(a1, a0);
                        float r0 = a0 - __uint_as_float(hp << 16);
                        float r1 = a1 - __uint_as_float(hp & 0xffff0000u);
                        uint32_t lp = cvt_bf2(r1, r0);
                        __nv_bfloat16* rw = g_Qp + ((size_t)(b * HH + hh) * NKP + n) * QK_COLS;
                        *reinterpret_cast<uint32_t*>(rw + d)      = hp;
                        *reinterpret_cast<uint32_t*>(rw + 24 + d) = lp;
                        *reinterpret_cast<uint32_t*>(rw + 48 + d) = hp;
                    } else if (o < 2 * CC) {
                        int oo = o - CC, hh = oo / DD, d = oo % DD;
                        uint32_t hp = cvt_bf2(v1, v0);
                        float r0 = v0 - __uint_as_float(hp << 16);
                        float r1 = v1 - __uint_as_float(hp & 0xffff0000u);
                        uint32_t lp = cvt_bf2(r1, r0);
                        __nv_bfloat16* rw = g_Kp + ((size_t)(b * HH + hh) * NKP + n) * QK_COLS;
                        *reinterpret_cast<uint32_t*>(rw + d)      = hp;
                        *reinterpret_cast<uint32_t*>(rw + 24 + d) = hp;
                        *reinterpret_cast<uint32_t*>(rw + 48 + d) = lp;
                    } else {
                        int oo = o - 2 * CC, hh = oo / DD, d = oo % DD;
                        __half2 h2 = __floats2half2_rn(v0, v1);
                        __half* rw = g_Vf + ((size_t)(b * HH + hh) * NKP + n) * V_COLS;
                        *reinterpret_cast<uint32_t*>(rw + d) = *reinterpret_cast<uint32_t*>(&h2);
                    }
                }
            }
        }
    }
}

// ---------------------------------------------------------------------------
// 2) Attention: flash w/ online max, 32 q-rows/warp (mt=2), Q frags from gmem,
//    packed-K bf16 S-pass, fp16 PV pass, cp.async double buffering.
// smem: KV double buffer only: 2 x (K 64x176 + V 64x80) = 32768 B
// ---------------------------------------------------------------------------
#define STG 16384
#define OK_ 0
#define OV_ 11264
#define ATT_SMEM 32768

__global__ __launch_bounds__(256, 1)
void attn_kernel() {
    extern __shared__ __align__(16) uint8_t dsm[];
    const uint32_t sb = smem_u32(dsm);

    const int tid = threadIdx.x;
    const int w   = tid >> 5;
    const int t   = tid & 31;
    const int bh  = blockIdx.z * HH + blockIdx.y;
    const int q0  = blockIdx.x * 256;

    // ---- K/V loader mapping (256 threads): which = tid>>6 ----
    const int lwhich = tid >> 6;
    const int lrow   = tid & 63;
    {
        uint32_t kb = sb;
        if (lwhich < 2) {
            const __nv_bfloat16* src = g_Kp + ((size_t)bh * NKP + lrow) * QK_COLS;
            uint32_t dst = kb + OK_ + lrow * 176;
            #pragma unroll
            for (int u = 0; u < 5; u++) {
                int g = lwhich * 5 + u;
                CP16(dst + g * 16, src + g * 8);
            }
        } else if (lwhich == 2) {
            const __half* src = g_Vf + ((size_t)bh * NKP + lrow) * V_COLS;
            uint32_t dst = kb + OV_ + lrow * 80;
            #pragma unroll
            for (int u = 0; u < 5; u++) CP16(dst + u * 16, src + u * 8);
        }
    }
    CP_COMMIT();

    // ---- Q fragments direct from gmem (one-time, 40 LDG.32) ----
    uint32_t aQ[2][5][4];
    {
        const uint8_t* qb = reinterpret_cast<const uint8_t*>(
            g_Qp + ((size_t)bh * NKP + q0 + w * 32 + (t >> 2)) * QK_COLS);
        #pragma unroll
        for (int mt = 0; mt < 2; mt++) {
            const uint8_t* qr = qb + mt * 16 * (QK_COLS * 2);
            #pragma unroll
            for (int s = 0; s < 5; s++) {
                const uint8_t* p = qr + s * 32 + (t & 3) * 4;
                aQ[mt][s][0] = *reinterpret_cast<const uint32_t*>(p);
                aQ[mt][s][1] = *reinterpret_cast<const uint32_t*>(p + 8 * (QK_COLS * 2));
                aQ[mt][s][2] = *reinterpret_cast<const uint32_t*>(p + 16);
                aQ[mt][s][3] = *reinterpret_cast<const uint32_t*>(p + 8 * (QK_COLS * 2) + 16);
            }
        }
    }

    float O[2][3][4];
    float lsum[2][2]   = {{0.f, 0.f}, {0.f, 0.f}};
    float rowmax[2][2] = {{-1e30f, -1e30f}, {-1e30f, -1e30f}};
    #pragma unroll
    for (int mt = 0; mt < 2; mt++)
        #pragma unroll
        for (int nt = 0; nt < 3; nt++)
            #pragma unroll
            for (int c = 0; c < 4; c++) O[mt][nt][c] = 0.f;

    for (int kt = 0; kt < KTILES; ++kt) {
        if (kt + 1 < KTILES) {
            const int j1 = (kt + 1) * 64;
            uint32_t kb = sb + ((kt + 1) & 1) * STG;
            if (lwhich < 2) {
                const __nv_bfloat16* src = g_Kp + ((size_t)bh * NKP + j1 + lrow) * QK_COLS;
                uint32_t dst = kb + OK_ + lrow * 176;
                #pragma unroll
                for (int u = 0; u < 5; u++) {
                    int g = lwhich * 5 + u;
                    CP16(dst + g * 16, src + g * 8);
                }
            } else if (lwhich == 2) {
                const __half* src = g_Vf + ((size_t)bh * NKP + j1 + lrow) * V_COLS;
                uint32_t dst = kb + OV_ + lrow * 80;
                #pragma unroll
                for (int u = 0; u < 5; u++) CP16(dst + u * 16, src + u * 8);
            }
            CP_COMMIT();
            CP_WAIT(1);
        } else {
            CP_WAIT(0);
        }
        __syncthreads();

        const uint32_t kb = sb + (kt & 1) * STG;
        const int j0 = kt * 64;

        // ---- S: one packed K=80 GEMM, both m-tiles share B-frags ----
        float C[2][8][4];
        #pragma unroll
        for (int mt = 0; mt < 2; mt++)
            #pragma unroll
            for (int nt = 0; nt < 8; nt++)
                #pragma unroll
                for (int c = 0; c < 4; c++) C[mt][nt][c] = 0.f;

        const uint32_t krow_off = (uint32_t)(t & 7) * 176 + (((t >> 3) & 1) ? 16u : 0u);
        #pragma unroll
        for (int s = 0; s < 5; s++) {
            uint32_t b0[8], b1[8];
            #pragma unroll
            for (int nt = 0; nt < 8; nt++)
                ldsm_x2(b0[nt], b1[nt], kb + OK_ + (uint32_t)nt * 8 * 176 + s * 32 + krow_off);
            #pragma unroll
            for (int nt = 0; nt < 8; nt++) {
                hmma_bf(C[0][nt], aQ[0][s][0], aQ[0][s][1], aQ[0][s][2], aQ[0][s][3],
                        b0[nt], b1[nt]);
                hmma_bf(C[1][nt], aQ[1][s][0], aQ[1][s][1], aQ[1][s][2], aQ[1][s][3],
                        b0[nt], b1[nt]);
            }
        }

        // ---- online max update (both m-tiles, interleaved) ----
        float tm[2][2];
        #pragma unroll
        for (int mt = 0; mt < 2; mt++) {
            float a = fmaxf(C[mt][0][0], C[mt][0][1]);
            float b = fmaxf(C[mt][0][2], C[mt][0][3]);
            #pragma unroll
            for (int nt = 1; nt < 8; nt++) {
                a = fmaxf(a, fmaxf(C[mt][nt][0], C[mt][nt][1]));
                b = fmaxf(b, fmaxf(C[mt][nt][2], C[mt][nt][3]));
            }
            tm[mt][0] = a; tm[mt][1] = b;
        }
        #pragma unroll
        for (int mt = 0; mt < 2; mt++)
            #pragma unroll
            for (int hf = 0; hf < 2; hf++) {
                tm[mt][hf] = fmaxf(tm[mt][hf], __shfl_xor_sync(0xffffffffu, tm[mt][hf], 1));
                tm[mt][hf] = fmaxf(tm[mt][hf], __shfl_xor_sync(0xffffffffu, tm[mt][hf], 2));
            }
        float M[2][2], f[2][2];
        #pragma unroll
        for (int mt = 0; mt < 2; mt++)
            #pragma unroll
            for (int hf = 0; hf < 2; hf++) {
                M[mt][hf] = fmaxf(rowmax[mt][hf], tm[mt][hf]);
                f[mt][hf] = ex2f(rowmax[mt][hf] - M[mt][hf]);
                rowmax[mt][hf] = M[mt][hf];
                lsum[mt][hf] *= f[mt][hf];
            }
        #pragma unroll
        for (int mt = 0; mt < 2; mt++)
            #pragma unroll
            for (int nt = 0; nt < 3; nt++) {
                O[mt][nt][0] *= f[mt][0]; O[mt][nt][1] *= f[mt][0];
                O[mt][nt][2] *= f[mt][1]; O[mt][nt][3] *= f[mt][1];
            }

        // ---- softmax: p = 2^(s - M) <= 1, pack fp16 pairs ----
        uint32_t PH[2][4][4];
        const bool edge = (j0 + 64 > NTOT);
        #pragma unroll
        for (int mt = 0; mt < 2; mt++) {
            #pragma unroll
            for (int nt = 0; nt < 8; nt++) {
                float p0 = ex2f(C[mt][nt][0] - M[mt][0]);
                float p1 = ex2f(C[mt][nt][1] - M[mt][0]);
                float p2 = ex2f(C[mt][nt][2] - M[mt][1]);
                float p3 = ex2f(C[mt][nt][3] - M[mt][1]);
                if (edge) {
                    int key0 = j0 + nt * 8 + (t & 3) * 2;
                    if (key0     >= NTOT) { p0 = 0.f; p2 = 0.f; }
                    if (key0 + 1 >= NTOT) { p1 = 0.f; p3 = 0.f; }
                }
                lsum[mt][0] += p0 + p1;
                lsum[mt][1] += p2 + p3;
                __half2 h01 = __floats2half2_rn(p0, p1);
                __half2 h23 = __floats2half2_rn(p2, p3);
                int ks = nt >> 1, half = nt & 1;
                PH[mt][ks][half * 2 + 0] = *reinterpret_cast<uint32_t*>(&h01);
                PH[mt][ks][half * 2 + 1] = *reinterpret_cast<uint32_t*>(&h23);
            }
        }

        // ---- O += ph * v (fp16; V frags shared across m-tiles) ----
        const uint32_t vrow_off = (uint32_t)(t & 15) * 80;
        #pragma unroll
        for (int ks = 0; ks < 4; ks++) {
            #pragma unroll
            for (int nt = 0; nt < 3; nt++) {
                uint32_t v0, v1;
                ldsm_x2_t(v0, v1, kb + OV_ + (uint32_t)(ks * 16) * 80 + nt * 16 + vrow_off);
                hmma_f16(O[0][nt], PH[0][ks][0], PH[0][ks][1], PH[0][ks][2], PH[0][ks][3], v0, v1);
                hmma_f16(O[1][nt], PH[1][ks][0], PH[1][ks][1], PH[1][ks][2], PH[1][ks][3], v0, v1);
            }
        }
        __syncthreads();
    }

    // ---- reduce row sums over quad lanes, invert ----
    #pragma unroll
    for (int mt = 0; mt < 2; mt++)
        #pragma unroll
        for (int hf = 0; hf < 2; hf++) {
            float v = lsum[mt][hf];
            v += __shfl_xor_sync(0xffffffffu, v, 1);
            v += __shfl_xor_sync(0xffffffffu, v, 2);
            lsum[mt][hf] = 1.f / v;
        }

    // ---- epilogue: O / l -> g_O ----
    #pragma unroll
    for (int mt = 0; mt < 2; mt++) {
        #pragma unroll
        for (int c = 0; c < 4; c++) {
            int row = w * 32 + mt * 16 + (t >> 2) + ((c >> 1) ? 8 : 0);
            int q = q0 + row;
            if (q < NTOT) {
                float inv = lsum[mt][c >> 1];
                #pragma unroll
                for (int nt = 0; nt < 3; nt++) {
                    int d = blockIdx.y * DD + nt * 8 + (t & 3) * 2 + (c & 1);
                    g_O[(size_t)(blockIdx.z * NTOT + q) * CC + d] = O[mt][nt][c] * inv;
                }
            }
        }
    }
}

// ---------------------------------------------------------------------------
// launch
// ---------------------------------------------------------------------------
extern "C" void kernel_launch(void* const* d_in, const int* in_sizes, int n_in,
                              void* d_out, int out_size) {
    const float* X  = nullptr;
    const float* S  = nullptr;
    const float* Wq = nullptr;
    const float* Wo = nullptr;
    const float* T  = nullptr;
    for (int i = 0; i < n_in; i++) {
        switch (in_sizes[i]) {
            case BB * NQ * CC:  X  = (const float*)d_in[i]; break;
            case BB * NS * CC:  S  = (const float*)d_in[i]; break;
            case 3 * CC * CC:   Wq = (const float*)d_in[i]; break;
            case CC * CC:       Wo = (const float*)d_in[i]; break;
            case HH:            T  = (const float*)d_in[i]; break;
        }
    }

    // 1) QKV projection (split tensor GEMM, concat fused, packed epilogue)
    {
        dim3 grid((MROWS + 63) / 64, (3 * CC) / 64);   // (129, 9)
        split_gemm_kernel<0><<<grid, 128>>>(X, S, Wq, T, nullptr);
    }
    // 2) attention (256 queries/CTA, 32 rows/warp)
    {
        cudaFuncSetAttribute(attn_kernel, cudaFuncAttributeMaxDynamicSharedMemorySize, ATT_SMEM);
        dim3 grid(QTILES, HH, BB);                      // (17, 8, 2)
        attn_kernel<<<grid, 256, ATT_SMEM>>>();
    }
    // 3) output projection (split tensor GEMM)
    {
        dim3 grid((BB * NQ) / 64, CC / 64);             // (128, 3)
        split_gemm_kernel<1><<<grid, 128>>>(nullptr, nullptr, Wo, nullptr, (float*)d_out);
    }
}

// round 13
// speedup vs baseline: 1.6002x; 1.2548x over previous
#include <cuda_runtime.h>
#include <cuda_bf16.h>
#include <cuda_fp16.h>
#include <cstdint>

// Problem constants
#define BB    2
#define NQ    4096
#define NS    8
#define NTOT  4104          // NQ + NS
#define CC    192
#define HH    8
#define DD    24            // CC / HH
#define MROWS (BB*NTOT)     // 8208
#define NKP   4352          // padded to 17*256 (query tiles of 256)
#define QTILES 17           // q-tiles of 256
#define KTILES2 33          // k-tiles of 128
#define LOG2E 1.4426950408889634f

// packed row widths (elements)
#define QK_COLS 88          // 80 data cols (5 ksteps x16) + 8 pad; 176B rows
#define V_COLS  40          // fp16: 24 data + ones col @24 + pad; 80B rows

typedef unsigned long long u64;

// ---------------------------------------------------------------------------
// helpers
// ---------------------------------------------------------------------------
__device__ __forceinline__ float ex2f(float x) {
    float r; asm("ex2.approx.f32 %0, %1;" : "=f"(r) : "f"(x)); return r;
}
__device__ __forceinline__ uint32_t cvt_bf2(float hi, float lo) {
    uint32_t r; asm("cvt.rn.bf16x2.f32 %0, %1, %2;" : "=r"(r) : "f"(hi), "f"(lo)); return r;
}
__device__ __forceinline__ uint32_t cvt_f16x2(float hi, float lo) {
    uint32_t r; asm("cvt.rn.f16x2.f32 %0, %1, %2;" : "=r"(r) : "f"(hi), "f"(lo)); return r;
}
__device__ __forceinline__ uint32_t ex2_f16x2(uint32_t x) {
    uint32_t r; asm("ex2.approx.f16x2 %0, %1;" : "=r"(r) : "r"(x)); return r;
}
// bf16 mma
__device__ __forceinline__ void hmma_bf(float (&c)[4],
                                        uint32_t a0, uint32_t a1, uint32_t a2, uint32_t a3,
                                        uint32_t b0, uint32_t b1) {
    asm volatile(
        "mma.sync.aligned.m16n8k16.row.col.f32.bf16.bf16.f32 "
        "{%0,%1,%2,%3},{%4,%5,%6,%7},{%8,%9},{%0,%1,%2,%3};"
        : "+f"(c[0]), "+f"(c[1]), "+f"(c[2]), "+f"(c[3])
        : "r"(a0), "r"(a1), "r"(a2), "r"(a3), "r"(b0), "r"(b1));
}
// fp16 mma (PV pass)
__device__ __forceinline__ void hmma_f16(float (&c)[4],
                                         uint32_t a0, uint32_t a1, uint32_t a2, uint32_t a3,
                                         uint32_t b0, uint32_t b1) {
    asm volatile(
        "mma.sync.aligned.m16n8k16.row.col.f32.f16.f16.f32 "
        "{%0,%1,%2,%3},{%4,%5,%6,%7},{%8,%9},{%0,%1,%2,%3};"
        : "+f"(c[0]), "+f"(c[1]), "+f"(c[2]), "+f"(c[3])
        : "r"(a0), "r"(a1), "r"(a2), "r"(a3), "r"(b0), "r"(b1));
}
__device__ __forceinline__ uint32_t smem_u32(const void* p) {
    uint32_t a;
    asm("{ .reg .u64 t; cvta.to.shared.u64 t, %1; cvt.u32.u64 %0, t; }" : "=r"(a) : "l"(p));
    return a;
}
__device__ __forceinline__ void ldsm_x2(uint32_t& r0, uint32_t& r1, uint32_t addr) {
    asm volatile("ldmatrix.sync.aligned.m8n8.x2.shared.b16 {%0,%1}, [%2];"
                 : "=r"(r0), "=r"(r1) : "r"(addr));
}
__device__ __forceinline__ void ldsm_x4(uint32_t& r0, uint32_t& r1, uint32_t& r2, uint32_t& r3,
                                        uint32_t addr) {
    asm volatile("ldmatrix.sync.aligned.m8n8.x4.shared.b16 {%0,%1,%2,%3}, [%4];"
                 : "=r"(r0), "=r"(r1), "=r"(r2), "=r"(r3) : "r"(addr));
}
__device__ __forceinline__ void ldsm_x2_t(uint32_t& r0, uint32_t& r1, uint32_t addr) {
    asm volatile("ldmatrix.sync.aligned.m8n8.x2.trans.shared.b16 {%0,%1}, [%2];"
                 : "=r"(r0), "=r"(r1) : "r"(addr));
}
#define CP16(dst, src) \
    asm volatile("cp.async.cg.shared.global [%0], [%1], 16;" :: "r"(dst), "l"(src))
#define CP_COMMIT() asm volatile("cp.async.commit_group;" ::: "memory")
#define CP_WAIT(n)  asm volatile("cp.async.wait_group %0;" :: "n"(n) : "memory")

// ---------------------------------------------------------------------------
// Scratch (device globals; zero-initialized -> pad columns/rows stay 0)
// g_Qp rows: [qh(0:24) | ql(24:48) | qh(48:72) | 0(72:88)]   (bf16, temp*log2e folded)
// g_Kp rows: [kh(0:24) | kh(24:48) | kl(48:72) | 0(72:88)]   (bf16)
// g_Vf rows: [v(0:24) fp16 | 1.0 @24 | 0]                     (fp16)
// ---------------------------------------------------------------------------
__device__ __align__(16) __nv_bfloat16 g_Qp[16*NKP*QK_COLS];
__device__ __align__(16) __nv_bfloat16 g_Kp[16*NKP*QK_COLS];
__device__ __align__(16) __half        g_Vf[16*NKP*V_COLS];
__device__ __align__(16) float g_O[BB*NTOT*CC];

// ---------------------------------------------------------------------------
// 1&3) Split-precision tensor GEMM (as R11/R12; MODE 0 V adds ones column).
// ---------------------------------------------------------------------------
#define GK_CHUNKS 6         // 192 / 32
#define GSTRIDE   104       // packed row stride in bf16 elems (208 B)

template<int MODE>
__global__ __launch_bounds__(128)
void split_gemm_kernel(const float* __restrict__ X,
                       const float* __restrict__ S,
                       const float* __restrict__ B,
                       const float* __restrict__ T,
                       float* __restrict__ out) {
    __shared__ __align__(16) __nv_bfloat16 sA[64 * GSTRIDE];
    __shared__ __align__(16) __nv_bfloat16 sB[64 * GSTRIDE];

    const int tid = threadIdx.x;
    const int w   = tid >> 5;
    const int t   = tid & 31;
    const int mw  = w >> 1;
    const int nw  = w & 1;
    const int m0  = blockIdx.x * 64;
    const int n0  = blockIdx.y * 64;

    const int srow = tid >> 1;
    const int scb  = tid & 1;

    const float* Arow = nullptr;
    if (MODE == 0) {
        int gr = m0 + srow;
        if (gr < MROWS) {
            int b = (gr >= NTOT) ? 1 : 0;
            int n = gr - b * NTOT;
            if (n < NQ) Arow = X + (size_t)(b * NQ + n) * CC;
            else        Arow = S + (size_t)(b * NS + (n - NQ)) * CC;
        }
    } else {
        int gr = m0 + srow;
        int b = gr >> 12;
        int n = gr & 4095;
        Arow = g_O + (size_t)(b * NTOT + n) * CC;
    }
    const float* Brow = B + (size_t)(n0 + srow) * CC;

    float av[16], bv[16];
    {
        #pragma unroll
        for (int q = 0; q < 4; q++) {
            float4 x = Arow ? *reinterpret_cast<const float4*>(Arow + scb * 16 + q * 4)
                            : make_float4(0.f, 0.f, 0.f, 0.f);
            av[q*4+0]=x.x; av[q*4+1]=x.y; av[q*4+2]=x.z; av[q*4+3]=x.w;
            float4 y = *reinterpret_cast<const float4*>(Brow + scb * 16 + q * 4);
            bv[q*4+0]=y.x; bv[q*4+1]=y.y; bv[q*4+2]=y.z; bv[q*4+3]=y.w;
        }
    }

    float C[2][4][4];
    #pragma unroll
    for (int mt = 0; mt < 2; mt++)
        #pragma unroll
        for (int nt = 0; nt < 4; nt++)
            #pragma unroll
            for (int c = 0; c < 4; c++) C[mt][nt][c] = 0.f;

    const uint32_t sAb = smem_u32(sA);
    const uint32_t sBb = smem_u32(sB);

    for (int kc = 0; kc < GK_CHUNKS; kc++) {
        {
            uint32_t ah[8], al[8], bh[8], bl[8];
            #pragma unroll
            for (int i = 0; i < 8; i++) {
                float a0 = av[2*i], a1 = av[2*i+1];
                uint32_t hp = cvt_bf2(a1, a0);
                float r0 = a0 - __uint_as_float(hp << 16);
                float r1 = a1 - __uint_as_float(hp & 0xffff0000u);
                ah[i] = hp; al[i] = cvt_bf2(r1, r0);
                float b0 = bv[2*i], b1 = bv[2*i+1];
                uint32_t hq = cvt_bf2(b1, b0);
                float s0 = b0 - __uint_as_float(hq << 16);
                float s1 = b1 - __uint_as_float(hq & 0xffff0000u);
                bh[i] = hq; bl[i] = cvt_bf2(s1, s0);
            }
            __nv_bfloat16* ar = sA + srow * GSTRIDE + scb * 16;
            __nv_bfloat16* br = sB + srow * GSTRIDE + scb * 16;
            *reinterpret_cast<uint4*>(ar)          = make_uint4(ah[0],ah[1],ah[2],ah[3]);
            *reinterpret_cast<uint4*>(ar + 8)      = make_uint4(ah[4],ah[5],ah[6],ah[7]);
            *reinterpret_cast<uint4*>(ar + 32)     = make_uint4(al[0],al[1],al[2],al[3]);
            *reinterpret_cast<uint4*>(ar + 40)     = make_uint4(al[4],al[5],al[6],al[7]);
            *reinterpret_cast<uint4*>(ar + 64)     = make_uint4(ah[0],ah[1],ah[2],ah[3]);
            *reinterpret_cast<uint4*>(ar + 72)     = make_uint4(ah[4],ah[5],ah[6],ah[7]);
            *reinterpret_cast<uint4*>(br)          = make_uint4(bh[0],bh[1],bh[2],bh[3]);
            *reinterpret_cast<uint4*>(br + 8)      = make_uint4(bh[4],bh[5],bh[6],bh[7]);
            *reinterpret_cast<uint4*>(br + 32)     = make_uint4(bh[0],bh[1],bh[2],bh[3]);
            *reinterpret_cast<uint4*>(br + 40)     = make_uint4(bh[4],bh[5],bh[6],bh[7]);
            *reinterpret_cast<uint4*>(br + 64)     = make_uint4(bl[0],bl[1],bl[2],bl[3]);
            *reinterpret_cast<uint4*>(br + 72)     = make_uint4(bl[4],bl[5],bl[6],bl[7]);
        }
        __syncthreads();

        if (kc + 1 < GK_CHUNKS) {
            int k0 = (kc + 1) * 32 + scb * 16;
            #pragma unroll
            for (int q = 0; q < 4; q++) {
                float4 x = Arow ? *reinterpret_cast<const float4*>(Arow + k0 + q * 4)
                                : make_float4(0.f, 0.f, 0.f, 0.f);
                av[q*4+0]=x.x; av[q*4+1]=x.y; av[q*4+2]=x.z; av[q*4+3]=x.w;
                float4 y = *reinterpret_cast<const float4*>(Brow + k0 + q * 4);
                bv[q*4+0]=y.x; bv[q*4+1]=y.y; bv[q*4+2]=y.z; bv[q*4+3]=y.w;
            }
        }

        #pragma unroll
        for (int s = 0; s < 6; s++) {
            uint32_t aA[2][4];
            #pragma unroll
            for (int mt = 0; mt < 2; mt++)
                ldsm_x4(aA[mt][0], aA[mt][1], aA[mt][2], aA[mt][3],
                        sAb + (uint32_t)(mw*32 + mt*16 + (t & 15)) * (GSTRIDE*2)
                            + ((t >> 4) & 1) * 16 + s * 32);
            uint32_t bB[4][2];
            #pragma unroll
            for (int nt = 0; nt < 4; nt++)
                ldsm_x2(bB[nt][0], bB[nt][1],
                        sBb + (uint32_t)(nw*32 + nt*8 + (t & 7)) * (GSTRIDE*2)
                            + ((t >> 3) & 1) * 16 + s * 32);
            #pragma unroll
            for (int mt = 0; mt < 2; mt++)
                #pragma unroll
                for (int nt = 0; nt < 4; nt++)
                    hmma_bf(C[mt][nt], aA[mt][0], aA[mt][1], aA[mt][2], aA[mt][3],
                            bB[nt][0], bB[nt][1]);
        }
        __syncthreads();
    }

    #pragma unroll
    for (int mt = 0; mt < 2; mt++) {
        #pragma unroll
        for (int cp = 0; cp < 2; cp++) {
            int row = m0 + mw * 32 + mt * 16 + (t >> 2) + cp * 8;
            if (MODE == 0 && row >= MROWS) continue;
            int b, n;
            if (MODE == 0) { b = (row >= NTOT) ? 1 : 0; n = row - b * NTOT; }
            #pragma unroll
            for (int nt = 0; nt < 4; nt++) {
                int o = n0 + nw * 32 + nt * 8 + (t & 3) * 2;
                float v0 = C[mt][nt][cp * 2];
                float v1 = C[mt][nt][cp * 2 + 1];
                if (MODE == 1) {
                    out[(size_t)row * CC + o]     = v0;
                    out[(size_t)row * CC + o + 1] = v1;
                } else {
                    if (o < CC) {
                        int hh = o / DD, d = o % DD;
                        float sc = T[hh] * LOG2E;
                        float a0 = v0 * sc, a1 = v1 * sc;
                        uint32_t hp = cvt_bf2(a1, a0);
                        float r0 = a0 - __uint_as_float(hp << 16);
                        float r1 = a1 - __uint_as_float(hp & 0xffff0000u);
                        uint32_t lp = cvt_bf2(r1, r0);
                        __nv_bfloat16* rw = g_Qp + ((size_t)(b * HH + hh) * NKP + n) * QK_COLS;
                        *reinterpret_cast<uint32_t*>(rw + d)      = hp;
                        *reinterpret_cast<uint32_t*>(rw + 24 + d) = lp;
                        *reinterpret_cast<uint32_t*>(rw + 48 + d) = hp;
                    } else if (o < 2 * CC) {
                        int oo = o - CC, hh = oo / DD, d = oo % DD;
                        uint32_t hp = cvt_bf2(v1, v0);
                        float r0 = v0 - __uint_as_float(hp << 16);
                        float r1 = v1 - __uint_as_float(hp & 0xffff0000u);
                        uint32_t lp = cvt_bf2(r1, r0);
                        __nv_bfloat16* rw = g_Kp + ((size_t)(b * HH + hh) * NKP + n) * QK_COLS;
                        *reinterpret_cast<uint32_t*>(rw + d)      = hp;
                        *reinterpret_cast<uint32_t*>(rw + 24 + d) = hp;
                        *reinterpret_cast<uint32_t*>(rw + 48 + d) = lp;
                    } else {
                        int oo = o - 2 * CC, hh = oo / DD, d = oo % DD;
                        __half2 h2 = __floats2half2_rn(v0, v1);
                        __half* rw = g_Vf + ((size_t)(b * HH + hh) * NKP + n) * V_COLS;
                        *reinterpret_cast<uint32_t*>(rw + d) = *reinterpret_cast<uint32_t*>(&h2);
                        if (d == 22)   // ones column for lsum-in-MMA
                            *reinterpret_cast<uint32_t*>(rw + 24) = 0x00003C00u;
                    }
                }
            }
        }
    }
}

// ---------------------------------------------------------------------------
// 2) Attention: flash w/ online max, 32 q-rows/warp, TK=128 staging (2 halves),
//    ex2.f16x2 softmax, lsum via ones-column in V (nt=4 PV), no edge checks.
// smem: 2 stages x (K 128x176 = 22528 | V 128x80 = 10240) = 65536 B
// ---------------------------------------------------------------------------
#define STG2 32768
#define OV2  22528
#define ATT_SMEM 65536

__global__ __launch_bounds__(256, 1)
void attn_kernel() {
    extern __shared__ __align__(16) uint8_t dsm[];
    const uint32_t sb = smem_u32(dsm);

    const int tid = threadIdx.x;
    const int w   = tid >> 5;
    const int t   = tid & 31;
    const int bh  = blockIdx.z * HH + blockIdx.y;
    const int q0  = blockIdx.x * 256;

    // ---- K/V loader mapping (256 threads, TK=128) ----
    const int krow = tid >> 1;                 // K: 128 rows x 10 chunks
    const int kgb  = (tid & 1) * 5;
    // V: 640 chunks linear
    auto load_tile = [&](int j0, uint32_t kb) {
        const __nv_bfloat16* ks = g_Kp + ((size_t)bh * NKP + j0 + krow) * QK_COLS;
        uint32_t kdst = kb + krow * 176;
        #pragma unroll
        for (int u = 0; u < 5; u++) CP16(kdst + (kgb + u) * 16, ks + (kgb + u) * 8);
        #pragma unroll
        for (int i = 0; i < 3; i++) {
            int c = tid + 256 * i;
            if (c < 640) {
                int vr = c / 5, vc = c % 5;
                CP16(kb + OV2 + vr * 80 + vc * 16,
                     g_Vf + ((size_t)bh * NKP + j0 + vr) * V_COLS + vc * 8);
            }
        }
    };
    load_tile(0, sb);
    CP_COMMIT();

    // ---- Q fragments direct from gmem (one-time) ----
    uint32_t aQ[2][5][4];
    {
        const uint8_t* qb = reinterpret_cast<const uint8_t*>(
            g_Qp + ((size_t)bh * NKP + q0 + w * 32 + (t >> 2)) * QK_COLS);
        #pragma unroll
        for (int mt = 0; mt < 2; mt++) {
            const uint8_t* qr = qb + mt * 16 * (QK_COLS * 2);
            #pragma unroll
            for (int s = 0; s < 5; s++) {
                const uint8_t* p = qr + s * 32 + (t & 3) * 4;
                aQ[mt][s][0] = *reinterpret_cast<const uint32_t*>(p);
                aQ[mt][s][1] = *reinterpret_cast<const uint32_t*>(p + 8 * (QK_COLS * 2));
                aQ[mt][s][2] = *reinterpret_cast<const uint32_t*>(p + 16);
                aQ[mt][s][3] = *reinterpret_cast<const uint32_t*>(p + 8 * (QK_COLS * 2) + 16);
            }
        }
    }

    float O[2][4][4];                     // nt=3 holds lsum in col 24
    float rowmax[2][2] = {{-1e30f, -1e30f}, {-1e30f, -1e30f}};
    #pragma unroll
    for (int mt = 0; mt < 2; mt++)
        #pragma unroll
        for (int nt = 0; nt < 4; nt++)
            #pragma unroll
            for (int c = 0; c < 4; c++) O[mt][nt][c] = 0.f;

    for (int kt = 0; kt < KTILES2; ++kt) {
        if (kt + 1 < KTILES2) {
            load_tile((kt + 1) * 128, sb + ((kt + 1) & 1) * STG2);
            CP_COMMIT();
            CP_WAIT(1);
        } else {
            CP_WAIT(0);
        }
        __syncthreads();

        const uint32_t kb = sb + (kt & 1) * STG2;
        const uint32_t krow_off = (uint32_t)(t & 7) * 176 + (((t >> 3) & 1) ? 16u : 0u);
        const uint32_t vrow_off = (uint32_t)(t & 15) * 80;

        #pragma unroll
        for (int half = 0; half < 2; half++) {
            const uint32_t kh_base = kb + (uint32_t)(half * 64) * 176;
            const uint32_t vh_base = kb + OV2 + (uint32_t)(half * 64) * 80;

            // ---- S: one packed K=80 GEMM, both m-tiles share B-frags ----
            float C[2][8][4];
            #pragma unroll
            for (int mt = 0; mt < 2; mt++)
                #pragma unroll
                for (int nt = 0; nt < 8; nt++)
                    #pragma unroll
                    for (int c = 0; c < 4; c++) C[mt][nt][c] = 0.f;

            #pragma unroll
            for (int s = 0; s < 5; s++) {
                uint32_t b0[8], b1[8];
                #pragma unroll
                for (int nt = 0; nt < 8; nt++)
                    ldsm_x2(b0[nt], b1[nt],
                            kh_base + (uint32_t)nt * 8 * 176 + s * 32 + krow_off);
                #pragma unroll
                for (int nt = 0; nt < 8; nt++) {
                    hmma_bf(C[0][nt], aQ[0][s][0], aQ[0][s][1], aQ[0][s][2], aQ[0][s][3],
                            b0[nt], b1[nt]);
                    hmma_bf(C[1][nt], aQ[1][s][0], aQ[1][s][1], aQ[1][s][2], aQ[1][s][3],
                            b0[nt], b1[nt]);
                }
            }

            // ---- online max update ----
            float tm[2][2];
            #pragma unroll
            for (int mt = 0; mt < 2; mt++) {
                float a = fmaxf(C[mt][0][0], C[mt][0][1]);
                float b = fmaxf(C[mt][0][2], C[mt][0][3]);
                #pragma unroll
                for (int nt = 1; nt < 8; nt++) {
                    a = fmaxf(a, fmaxf(C[mt][nt][0], C[mt][nt][1]));
                    b = fmaxf(b, fmaxf(C[mt][nt][2], C[mt][nt][3]));
                }
                tm[mt][0] = a; tm[mt][1] = b;
            }
            #pragma unroll
            for (int mt = 0; mt < 2; mt++)
                #pragma unroll
                for (int hf = 0; hf < 2; hf++) {
                    tm[mt][hf] = fmaxf(tm[mt][hf], __shfl_xor_sync(0xffffffffu, tm[mt][hf], 1));
                    tm[mt][hf] = fmaxf(tm[mt][hf], __shfl_xor_sync(0xffffffffu, tm[mt][hf], 2));
                }
            float M[2][2], f[2][2];
            #pragma unroll
            for (int mt = 0; mt < 2; mt++)
                #pragma unroll
                for (int hf = 0; hf < 2; hf++) {
                    M[mt][hf] = fmaxf(rowmax[mt][hf], tm[mt][hf]);
                    f[mt][hf] = ex2f(rowmax[mt][hf] - M[mt][hf]);
                    rowmax[mt][hf] = M[mt][hf];
                }
            #pragma unroll
            for (int mt = 0; mt < 2; mt++)
                #pragma unroll
                for (int nt = 0; nt < 4; nt++) {   // includes lsum column
                    O[mt][nt][0] *= f[mt][0]; O[mt][nt][1] *= f[mt][0];
                    O[mt][nt][2] *= f[mt][1]; O[mt][nt][3] *= f[mt][1];
                }

            // ---- softmax: p = ex2.f16x2(s - M), PH fragments directly ----
            uint32_t PH[2][4][4];
            #pragma unroll
            for (int mt = 0; mt < 2; mt++) {
                #pragma unroll
                for (int nt = 0; nt < 8; nt++) {
                    uint32_t x01 = cvt_f16x2(C[mt][nt][1] - M[mt][0], C[mt][nt][0] - M[mt][0]);
                    uint32_t x23 = cvt_f16x2(C[mt][nt][3] - M[mt][1], C[mt][nt][2] - M[mt][1]);
                    int ks = nt >> 1, hf2 = nt & 1;
                    PH[mt][ks][hf2 * 2 + 0] = ex2_f16x2(x01);
                    PH[mt][ks][hf2 * 2 + 1] = ex2_f16x2(x23);
                }
            }

            // ---- O += ph * v (nt=4: cols 0..23 data, col 24 = ones/lsum) ----
            #pragma unroll
            for (int ks = 0; ks < 4; ks++) {
                #pragma unroll
                for (int nt = 0; nt < 4; nt++) {
                    uint32_t v0, v1;
                    ldsm_x2_t(v0, v1, vh_base + (uint32_t)(ks * 16) * 80 + nt * 16 + vrow_off);
                    hmma_f16(O[0][nt], PH[0][ks][0], PH[0][ks][1], PH[0][ks][2], PH[0][ks][3], v0, v1);
                    hmma_f16(O[1][nt], PH[1][ks][0], PH[1][ks][1], PH[1][ks][2], PH[1][ks][3], v0, v1);
                }
            }
        }
        __syncthreads();
    }

    // ---- lsum lives in O[mt][3] col 24 (lanes with (t&3)==0); broadcast ----
    float inv[2][2];
    #pragma unroll
    for (int mt = 0; mt < 2; mt++)
        #pragma unroll
        for (int hf = 0; hf < 2; hf++) {
            float v = __shfl_sync(0xffffffffu, O[mt][3][hf * 2], (t >> 2) << 2);
            inv[mt][hf] = 1.f / v;
        }

    // ---- epilogue: O / l -> g_O ----
    #pragma unroll
    for (int mt = 0; mt < 2; mt++) {
        #pragma unroll
        for (int c = 0; c < 4; c++) {
            int row = w * 32 + mt * 16 + (t >> 2) + ((c >> 1) ? 8 : 0);
            int q = q0 + row;
            if (q < NTOT) {
                float iv = inv[mt][c >> 1];
                #pragma unroll
                for (int nt = 0; nt < 3; nt++) {
                    int d = blockIdx.y * DD + nt * 8 + (t & 3) * 2 + (c & 1);
                    g_O[(size_t)(blockIdx.z * NTOT + q) * CC + d] = O[mt][nt][c] * iv;
                }
            }
        }
    }
}

// ---------------------------------------------------------------------------
// launch
// ---------------------------------------------------------------------------
extern "C" void kernel_launch(void* const* d_in, const int* in_sizes, int n_in,
                              void* d_out, int out_size) {
    const float* X  = nullptr;
    const float* S  = nullptr;
    const float* Wq = nullptr;
    const float* Wo = nullptr;
    const float* T  = nullptr;
    for (int i = 0; i < n_in; i++) {
        switch (in_sizes[i]) {
            case BB * NQ * CC:  X  = (const float*)d_in[i]; break;
            case BB * NS * CC:  S  = (const float*)d_in[i]; break;
            case 3 * CC * CC:   Wq = (const float*)d_in[i]; break;
            case CC * CC:       Wo = (const float*)d_in[i]; break;
            case HH:            T  = (const float*)d_in[i]; break;
        }
    }

    // 1) QKV projection (split tensor GEMM, concat fused, packed epilogue)
    {
        dim3 grid((MROWS + 63) / 64, (3 * CC) / 64);   // (129, 9)
        split_gemm_kernel<0><<<grid, 128>>>(X, S, Wq, T, nullptr);
    }
    // 2) attention (256 queries/CTA, 32 rows/warp, TK=128)
    {
        cudaFuncSetAttribute(attn_kernel, cudaFuncAttributeMaxDynamicSharedMemorySize, ATT_SMEM);
        dim3 grid(QTILES, HH, BB);                      // (17, 8, 2)
        attn_kernel<<<grid, 256, ATT_SMEM>>>();
    }
    // 3) output projection (split tensor GEMM)
    {
        dim3 grid((BB * NQ) / 64, CC / 64);             // (128, 3)
        split_gemm_kernel<1><<<grid, 128>>>(nullptr, nullptr, Wo, nullptr, (float*)d_out);
    }
}